// round 13
// baseline (speedup 1.0000x reference)
#include <cuda_runtime.h>

#define LEAK   0.1f
#define BN_EPS 1e-5f

// problem dims
#define B_   16
#define CH   32
#define H0c  48
#define H2c  46
#define H3c  44
#define D0   2304
#define D1   2116
#define D2   1936
#define NF   512
#define BI   512
#define OC   1024
#define BOC  16384
#define NN2  (NF * NF)
#define OSL  (512 * D2)

// ---------------- scratch ----------------
__device__ float g_Sp[12 * NN2];        // VQ0 [0:8) (VQ1 reuses [0:4)); DOT1 [8:12)
__device__ float g_G[18 * NN2];         // G partials (t*2+s)
__device__ float g_h1[BI * D1];
__device__ float g_Cs[9 * NF * D2];     // shifted cb_fdw2; later reused for out partials (4 slices)
__device__ float g_A[BI * NF];
__device__ int   g_cnt[B_ * CH * NF];
__device__ int   g_idx2[BOC];
__device__ int   g_pair[NF * CH];
__device__ float g_qw1[CH * 9];
__device__ float g_qw2[CH * 9];
__device__ float g_qpw1[OC];
__device__ float g_qpw2[OC];
__device__ float g_nfdw[NF];
__device__ float g_nfpw[NF];
__device__ float g_nfdw2[NF];
__device__ float g_nfpw2[NF];

// ---------------- packed fp32x2 helpers ----------------
#define FMA2(acc, a, b) asm("fma.rn.f32x2 %0, %1, %2, %0;" : "+l"(acc) : "l"(a), "l"(b))
#define DUP2(d, x) asm("mov.b64 %0, {%1, %1};" : "=l"(d) : "r"(__float_as_uint(x)))

// ================= fused prep: shift_prep + norms + quantw =================
__global__ void prep_kernel(const float* __restrict__ cb_fdw, const float* __restrict__ cb_fpw,
                            const float* __restrict__ cb_fdw2, const float* __restrict__ cb_fpw2,
                            const float* __restrict__ dw1, const float* __restrict__ pw1,
                            const float* __restrict__ dw2, const float* __restrict__ pw2,
                            const float* __restrict__ cdw, const float* __restrict__ cpw,
                            const float* __restrict__ cdw2, const float* __restrict__ cpw2) {
    int b = blockIdx.x;
    if (b < 9 * NF) {
        int k = b & (NF - 1), t = b >> 9;
        int ty = t / 3, tx = t - ty * 3;
        const float* src = cb_fdw2 + (long)k * D1;
        float* dst = g_Cs + ((long)t * NF + k) * D2;
        for (int p = threadIdx.x; p < D2; p += 256) {
            int py = p / H3c, px = p - py * H3c;
            dst[p] = src[(py + ty) * H2c + px + tx];
        }
        return;
    }
    b -= 9 * NF;
    if (b < 4 * NF) {
        int row = b & (NF - 1), which = b >> 9;
        const float* src; int D; float* dst;
        if (which == 0)      { src = cb_fdw;  D = D0; dst = g_nfdw;  }
        else if (which == 1) { src = cb_fpw;  D = D1; dst = g_nfpw;  }
        else if (which == 2) { src = cb_fdw2; D = D1; dst = g_nfdw2; }
        else                 { src = cb_fpw2; D = D2; dst = g_nfpw2; }
        const float* p = src + (long)row * D;
        float s = 0.f;
        for (int i = threadIdx.x; i < D; i += 256) { float v = p[i]; s += v * v; }
        __shared__ float sm[256];
        sm[threadIdx.x] = s; __syncthreads();
        for (int o = 128; o > 0; o >>= 1) {
            if (threadIdx.x < o) sm[threadIdx.x] += sm[threadIdx.x + o];
            __syncthreads();
        }
        if (threadIdx.x == 0) dst[row] = sm[0];
        return;
    }
    // weight VQ (one block)
    int t = threadIdx.x;
    if (t < 32) {
        float w[9];
        for (int j = 0; j < 9; j++) w[j] = dw1[t * 9 + j];
        float bd = 3.4e38f; int bk = 0;
        for (int k = 0; k < 256; k++) {
            float d = 0.f;
            for (int j = 0; j < 9; j++) { float e = w[j] - cdw[k * 9 + j]; d += e * e; }
            if (d < bd) { bd = d; bk = k; }
        }
        for (int j = 0; j < 9; j++) g_qw1[t * 9 + j] = cdw[bk * 9 + j];
        for (int j = 0; j < 9; j++) w[j] = dw2[t * 9 + j];
        bd = 3.4e38f; bk = 0;
        for (int k = 0; k < 256; k++) {
            float d = 0.f;
            for (int j = 0; j < 9; j++) { float e = w[j] - cdw2[k * 9 + j]; d += e * e; }
            if (d < bd) { bd = d; bk = k; }
        }
        for (int j = 0; j < 9; j++) g_qw2[t * 9 + j] = cdw2[bk * 9 + j];
    }
    for (int c = t; c < OC; c += 256) {
        float w = pw1[c]; float bd = 3.4e38f; int bk = 0;
        for (int k = 0; k < 256; k++) { float e = w - cpw[k]; float d = e * e; if (d < bd) { bd = d; bk = k; } }
        g_qpw1[c] = cpw[bk];
        w = pw2[c]; bd = 3.4e38f; bk = 0;
        for (int k = 0; k < 256; k++) { float e = w - cpw2[k]; float d = e * e; if (d < bd) { bd = d; bk = k; } }
        g_qpw2[c] = cpw2[bk];
    }
}

__device__ __forceinline__ float4 ld4_guard(const float* p, int k, int kend) {
    return (k < kend) ? *(const float4*)(p + k) : make_float4(0.f, 0.f, 0.f, 0.f);
}

// ================= NT GEMM core (R6 best): compact A, direct-u64 B, K-step 16 =================
__device__ __forceinline__ void nt_core(const float* __restrict__ A, const float* __restrict__ B,
                                        float* __restrict__ C, int ldk, int kb, int kend) {
    __shared__ float As[2][16][128];
    __shared__ float Bs[2][16][128];
    int tid = threadIdx.x;
    int m0 = blockIdx.y * 128, n0 = blockIdx.x * 128;
    int lr = tid >> 1, lc = (tid & 1) * 8;
    int tx = tid & 15, ty = tid >> 4;

    const float* Ab = A + (long)(m0 + lr) * ldk;
    const float* Bb = B + (long)(n0 + lr) * ldk;

    unsigned long long acc[8][4] = {};

    {
        float4 aL = ld4_guard(Ab, kb + lc, kend);
        float4 aH = ld4_guard(Ab, kb + lc + 4, kend);
        float4 bL = ld4_guard(Bb, kb + lc, kend);
        float4 bH = ld4_guard(Bb, kb + lc + 4, kend);
        As[0][lc + 0][lr] = aL.x; As[0][lc + 1][lr] = aL.y; As[0][lc + 2][lr] = aL.z; As[0][lc + 3][lr] = aL.w;
        As[0][lc + 4][lr] = aH.x; As[0][lc + 5][lr] = aH.y; As[0][lc + 6][lr] = aH.z; As[0][lc + 7][lr] = aH.w;
        Bs[0][lc + 0][lr] = bL.x; Bs[0][lc + 1][lr] = bL.y; Bs[0][lc + 2][lr] = bL.z; Bs[0][lc + 3][lr] = bL.w;
        Bs[0][lc + 4][lr] = bH.x; Bs[0][lc + 5][lr] = bH.y; Bs[0][lc + 6][lr] = bH.z; Bs[0][lc + 7][lr] = bH.w;
    }
    __syncthreads();

    int buf = 0;
    for (int k0 = kb; k0 < kend; k0 += 16) {
        bool nxt = (k0 + 16) < kend;
        float4 naL, naH, nbL, nbH;
        if (nxt) {
            naL = ld4_guard(Ab, k0 + 16 + lc, kend);
            naH = ld4_guard(Ab, k0 + 16 + lc + 4, kend);
            nbL = ld4_guard(Bb, k0 + 16 + lc, kend);
            nbH = ld4_guard(Bb, k0 + 16 + lc + 4, kend);
        }
#pragma unroll
        for (int kk = 0; kk < 16; kk++) {
            float4 a0 = *(const float4*)&As[buf][kk][ty * 4];
            float4 a1 = *(const float4*)&As[buf][kk][64 + ty * 4];
            ulonglong2 b01 = *(const ulonglong2*)&Bs[buf][kk][tx * 4];
            ulonglong2 b23 = *(const ulonglong2*)&Bs[buf][kk][64 + tx * 4];
            float ar[8] = { a0.x, a0.y, a0.z, a0.w, a1.x, a1.y, a1.z, a1.w };
#pragma unroll
            for (int i = 0; i < 8; i++) {
                unsigned long long ap; DUP2(ap, ar[i]);
                FMA2(acc[i][0], ap, b01.x); FMA2(acc[i][1], ap, b01.y);
                FMA2(acc[i][2], ap, b23.x); FMA2(acc[i][3], ap, b23.y);
            }
        }
        if (nxt) {
            int bN = buf ^ 1;
            As[bN][lc + 0][lr] = naL.x; As[bN][lc + 1][lr] = naL.y; As[bN][lc + 2][lr] = naL.z; As[bN][lc + 3][lr] = naL.w;
            As[bN][lc + 4][lr] = naH.x; As[bN][lc + 5][lr] = naH.y; As[bN][lc + 6][lr] = naH.z; As[bN][lc + 7][lr] = naH.w;
            Bs[bN][lc + 0][lr] = nbL.x; Bs[bN][lc + 1][lr] = nbL.y; Bs[bN][lc + 2][lr] = nbL.z; Bs[bN][lc + 3][lr] = nbL.w;
            Bs[bN][lc + 4][lr] = nbH.x; Bs[bN][lc + 5][lr] = nbH.y; Bs[bN][lc + 6][lr] = nbH.z; Bs[bN][lc + 7][lr] = nbH.w;
            __syncthreads();
            buf = bN;
        }
    }

#pragma unroll
    for (int i = 0; i < 8; i++) {
        int m = m0 + (i < 4 ? ty * 4 + i : 64 + ty * 4 + i - 4);
        float* Cr = C + (long)m * NF + n0;
        *(unsigned long long*)(Cr + tx * 4)          = acc[i][0];
        *(unsigned long long*)(Cr + tx * 4 + 2)      = acc[i][1];
        *(unsigned long long*)(Cr + 64 + tx * 4)     = acc[i][2];
        *(unsigned long long*)(Cr + 64 + tx * 4 + 2) = acc[i][3];
    }
}

// -------- VQ0: split-K 8 (z 0-7, chunk 288) -> Sp[0..7] --------
__global__ void __launch_bounds__(256) gemm_vq0(const float* __restrict__ x,
                                                const float* __restrict__ cbfdw) {
    int z = blockIdx.z;
    nt_core(x, cbfdw, g_Sp + (long)z * NN2, D0, z * 288, z * 288 + 288);
}

// -------- DOT1 (aux): split-K 4 (z 0-3, chunk 532) -> Sp[8..11] --------
__global__ void __launch_bounds__(256) gemm_dot1(const float* __restrict__ cbfpw,
                                                 const float* __restrict__ cbfdw2) {
    int s = blockIdx.z;
    int kb = s * 532, kend = min(D1, kb + 532);
    nt_core(cbfpw, cbfdw2, g_Sp + (long)(8 + s) * NN2, D1, kb, kend);
}

// -------- VQ1 (main): split-K 4 (z 0-3) -> Sp[0..3] (after am0 consumed VQ0) --------
__global__ void __launch_bounds__(256) gemm_vq1(const float* __restrict__ cbfpw) {
    int s = blockIdx.z;
    int kb = s * 532, kend = min(D1, kb + 532);
    nt_core(g_h1, cbfpw, g_Sp + (long)s * NN2, D1, kb, kend);
}

// -------- G: split-K 2 x 9 tiles = 18 z-slices (288 blocks, 2 CTA/SM waves) --------
__global__ void __launch_bounds__(256) gemm_g(const float* __restrict__ cbfpw2) {
    int z = blockIdx.z, t = z >> 1, s = z & 1;
    int kb = s * 968;
    nt_core(g_Cs + (long)t * NF * D2, cbfpw2, g_G + (long)z * NN2, D2, kb, kb + 968);
}

// -------- out GEMM: partial C = A (512x128 K-chunk) * B (512x1936), split-K 4 --------
__global__ void __launch_bounds__(256) sgemm_nn_split(
    const float* __restrict__ A, const float* __restrict__ B, float* __restrict__ C)
{
    const int N = D2, K = NF;
    int kb = blockIdx.z * 128, kend = kb + 128;
    C += (long)blockIdx.z * OSL;

    __shared__ float As[2][16][128];
    __shared__ float Bs[2][16][128];

    int tid = threadIdx.x;
    int m0 = blockIdx.y * 128, n0 = blockIdx.x * 128;
    int lr = tid >> 1, lc = (tid & 1) * 8;
    int krow = tid >> 4, nb_ = (tid & 15) * 8;
    int tx = tid & 15, ty = tid >> 4;

    const float* Ab = A + (long)(m0 + lr) * K;
    unsigned long long acc[8][4] = {};

    {
        float4 aL = *(const float4*)(Ab + kb + lc);
        float4 aH = *(const float4*)(Ab + kb + lc + 4);
        As[0][lc + 0][lr] = aL.x; As[0][lc + 1][lr] = aL.y; As[0][lc + 2][lr] = aL.z; As[0][lc + 3][lr] = aL.w;
        As[0][lc + 4][lr] = aH.x; As[0][lc + 5][lr] = aH.y; As[0][lc + 6][lr] = aH.z; As[0][lc + 7][lr] = aH.w;
        float4 bL = (n0 + nb_ < N) ? *(const float4*)(B + (long)(kb + krow) * N + n0 + nb_)
                                   : make_float4(0.f, 0.f, 0.f, 0.f);
        float4 bH = (n0 + nb_ + 4 < N) ? *(const float4*)(B + (long)(kb + krow) * N + n0 + nb_ + 4)
                                       : make_float4(0.f, 0.f, 0.f, 0.f);
        *(float4*)&Bs[0][krow][nb_] = bL;
        *(float4*)&Bs[0][krow][nb_ + 4] = bH;
    }
    __syncthreads();

    int buf = 0;
    for (int k0 = kb; k0 < kend; k0 += 16) {
        bool nxt = (k0 + 16) < kend;
        float4 naL, naH, nbL, nbH;
        if (nxt) {
            naL = *(const float4*)(Ab + k0 + 16 + lc);
            naH = *(const float4*)(Ab + k0 + 16 + lc + 4);
            nbL = (n0 + nb_ < N) ? *(const float4*)(B + (long)(k0 + 16 + krow) * N + n0 + nb_)
                                 : make_float4(0.f, 0.f, 0.f, 0.f);
            nbH = (n0 + nb_ + 4 < N) ? *(const float4*)(B + (long)(k0 + 16 + krow) * N + n0 + nb_ + 4)
                                     : make_float4(0.f, 0.f, 0.f, 0.f);
        }
#pragma unroll
        for (int kk = 0; kk < 16; kk++) {
            float4 a0 = *(const float4*)&As[buf][kk][ty * 4];
            float4 a1 = *(const float4*)&As[buf][kk][64 + ty * 4];
            ulonglong2 b01 = *(const ulonglong2*)&Bs[buf][kk][tx * 4];
            ulonglong2 b23 = *(const ulonglong2*)&Bs[buf][kk][64 + tx * 4];
            float ar[8] = { a0.x, a0.y, a0.z, a0.w, a1.x, a1.y, a1.z, a1.w };
#pragma unroll
            for (int i = 0; i < 8; i++) {
                unsigned long long ap; DUP2(ap, ar[i]);
                FMA2(acc[i][0], ap, b01.x); FMA2(acc[i][1], ap, b01.y);
                FMA2(acc[i][2], ap, b23.x); FMA2(acc[i][3], ap, b23.y);
            }
        }
        if (nxt) {
            int bN = buf ^ 1;
            As[bN][lc + 0][lr] = naL.x; As[bN][lc + 1][lr] = naL.y; As[bN][lc + 2][lr] = naL.z; As[bN][lc + 3][lr] = naL.w;
            As[bN][lc + 4][lr] = naH.x; As[bN][lc + 5][lr] = naH.y; As[bN][lc + 6][lr] = naH.z; As[bN][lc + 7][lr] = naH.w;
            *(float4*)&Bs[bN][krow][nb_] = nbL;
            *(float4*)&Bs[bN][krow][nb_ + 4] = nbH;
            __syncthreads();
            buf = bN;
        }
    }

#pragma unroll
    for (int i = 0; i < 8; i++) {
        int m = m0 + (i < 4 ? ty * 4 + i : 64 + ty * 4 + i - 4);
        float* Cr = C + (long)m * N;
#pragma unroll
        for (int jp = 0; jp < 4; jp++) {
            int n = n0 + (jp < 2 ? tx * 4 + jp * 2 : 64 + tx * 4 + (jp - 2) * 2);
            if (n < N) *(unsigned long long*)(Cr + n) = acc[i][jp];
        }
    }
}

// ---------------- BN + lrelu reduce of 4 out partials ----------------
__global__ void bn_reduce(const float* __restrict__ P, float* __restrict__ out,
                          const float* __restrict__ gamma, const float* __restrict__ beta,
                          const float* __restrict__ rmean, const float* __restrict__ rvar) {
    int m = blockIdx.x;
    int g = m & 31;
    float sc = rsqrtf(rvar[g] + BN_EPS) * gamma[g];
    float mu = rmean[g], bt = beta[g];
    const float* p0 = P + (long)m * D2;
    float* o = out + (long)m * D2;
    for (int n = threadIdx.x; n < D2; n += 256) {
        float v = p0[n] + p0[n + OSL] + p0[n + 2 * OSL] + p0[n + 3 * OSL];
        v = (v - mu) * sc + bt;
        o[n] = (v >= 0.f) ? v : LEAK * v;
    }
}

// ============ fused argmin(VQ0, 8 partials) + conv1 + lrelu ============
__global__ void am0_conv1(const float* __restrict__ Sp, const float* __restrict__ cb_fdw) {
    int v = blockIdx.x;
    int i = v & 31;
    __shared__ float sd[256]; __shared__ int si[256];
    __shared__ float w[9];
    __shared__ int s_idx;
    if (threadIdx.x < 9) w[threadIdx.x] = g_qw1[i * 9 + threadIdx.x];
    float bd = 3.4e38f; int bk = 0;
    for (int k = threadIdx.x; k < NF; k += 256) {
        float s = 0.f;
#pragma unroll
        for (int sp = 0; sp < 8; sp++)
            s += Sp[((long)sp * NF + v) * NF + k];
        float d = g_nfdw[k] - 2.0f * s;
        if (d < bd) { bd = d; bk = k; }
    }
    sd[threadIdx.x] = bd; si[threadIdx.x] = bk; __syncthreads();
    for (int o = 128; o > 0; o >>= 1) {
        if (threadIdx.x < o) {
            float d2 = sd[threadIdx.x + o]; int k2 = si[threadIdx.x + o];
            if (d2 < sd[threadIdx.x] || (d2 == sd[threadIdx.x] && k2 < si[threadIdx.x])) {
                sd[threadIdx.x] = d2; si[threadIdx.x] = k2;
            }
        }
        __syncthreads();
    }
    if (threadIdx.x == 0) s_idx = si[0];
    __syncthreads();
    const float* src = cb_fdw + (long)s_idx * D0;
    for (int p = threadIdx.x; p < D1; p += 256) {
        int py = p / H2c, px = p - py * H2c;
        const float* s0 = src + py * H0c + px;
        float acc = s0[0] * w[0] + s0[1] * w[1] + s0[2] * w[2]
                  + s0[H0c] * w[3] + s0[H0c + 1] * w[4] + s0[H0c + 2] * w[5]
                  + s0[2 * H0c] * w[6] + s0[2 * H0c + 1] * w[7] + s0[2 * H0c + 2] * w[8];
        g_h1[(long)v * D1 + p] = (acc >= 0.f) ? acc : LEAK * acc;
    }
}

// ============ fused argmin(VQ1, 4 partials) + idx2 scan (DOT 4 partials) ============
__global__ void am1_idx2(const float* __restrict__ Vp, const float* __restrict__ DOT) {
    int vbi = blockIdx.x;
    int b = vbi >> 5, i = vbi & 31;
    __shared__ float sd[256]; __shared__ int si[256];
    __shared__ int s_j;
    float bd = 3.4e38f; int bk = 0;
    for (int k = threadIdx.x; k < NF; k += 256) {
        float s = 0.f;
#pragma unroll
        for (int sp = 0; sp < 4; sp++)
            s += Vp[((long)sp * NF + vbi) * NF + k];
        float d = g_nfpw[k] - 2.0f * s;
        if (d < bd) { bd = d; bk = k; }
    }
    sd[threadIdx.x] = bd; si[threadIdx.x] = bk; __syncthreads();
    for (int o = 128; o > 0; o >>= 1) {
        if (threadIdx.x < o) {
            float d2 = sd[threadIdx.x + o]; int k2 = si[threadIdx.x + o];
            if (d2 < sd[threadIdx.x] || (d2 == sd[threadIdx.x] && k2 < si[threadIdx.x])) {
                sd[threadIdx.x] = d2; si[threadIdx.x] = k2;
            }
        }
        __syncthreads();
    }
    if (threadIdx.x == 0) s_j = si[0];
    __syncthreads();
    int j = s_j;
    __shared__ float dr[NF]; __shared__ float nn[NF];
    for (int k = threadIdx.x; k < NF; k += 256) {
        float v = 0.f;
#pragma unroll
        for (int sp = 0; sp < 4; sp++)
            v += DOT[((long)sp * NF + j) * NF + k];
        dr[k] = v;
        nn[k] = g_nfdw2[k];
    }
    __syncthreads();
    int warp = threadIdx.x >> 5, lane = threadIdx.x & 31;
    for (int o = warp; o < CH; o += 8) {
        float s = g_qpw1[o * 32 + i];
        float bd2 = 3.4e38f; int bk2 = 0;
        for (int k = lane; k < NF; k += 32) {
            float d = nn[k] - 2.0f * s * dr[k];
            if (d < bd2) { bd2 = d; bk2 = k; }
        }
        for (int off = 16; off > 0; off >>= 1) {
            float d2 = __shfl_down_sync(0xffffffffu, bd2, off);
            int k2 = __shfl_down_sync(0xffffffffu, bk2, off);
            if (d2 < bd2 || (d2 == bd2 && k2 < bk2)) { bd2 = d2; bk2 = k2; }
        }
        if (lane == 0) g_idx2[b * OC + o * 32 + i] = bk2;
    }
}

// ---------------- pair argmin over m per (k,o), G has 2 partials per tile ----------------
__global__ void __launch_bounds__(256) pair_kernel() {
    int k = blockIdx.x;
    __shared__ float gs[9][NF];
    __shared__ float nn[NF];
    __shared__ float ws[CH * 9];
    for (int t = 0; t < 9; t++)
        for (int m = threadIdx.x; m < NF; m += 256)
            gs[t][m] = g_G[((long)(2 * t) * NF + k) * NF + m]
                     + g_G[((long)(2 * t + 1) * NF + k) * NF + m];
    for (int i = threadIdx.x; i < CH * 9; i += 256) ws[i] = g_qw2[i];
    for (int m = threadIdx.x; m < NF; m += 256) nn[m] = g_nfpw2[m];
    __syncthreads();
    int warp = threadIdx.x >> 5, lane = threadIdx.x & 31;
    for (int o = warp; o < CH; o += 8) {
        float wv[9];
#pragma unroll
        for (int t = 0; t < 9; t++) wv[t] = ws[o * 9 + t];
        float bd = 3.4e38f; int bk = 0;
        for (int m = lane; m < NF; m += 32) {
            float T = 0.f;
#pragma unroll
            for (int t = 0; t < 9; t++) T += wv[t] * gs[t][m];
            float d = nn[m] - 2.0f * T;
            if (d < bd) { bd = d; bk = m; }
        }
        for (int off = 16; off > 0; off >>= 1) {
            float d2 = __shfl_down_sync(0xffffffffu, bd, off);
            int k2 = __shfl_down_sync(0xffffffffu, bk, off);
            if (d2 < bd || (d2 == bd && k2 < bk)) { bd = d2; bk = k2; }
        }
        if (lane == 0) g_pair[k * CH + o] = bk;
    }
}

// ---------------- histogram ----------------
__global__ void cnt_kernel() {
    int bo = blockIdx.x;
    __shared__ int c[NF];
    for (int m = threadIdx.x; m < NF; m += 256) c[m] = 0;
    __syncthreads();
    if (threadIdx.x == 0) {
        int b = bo >> 5, o = bo & 31;
        for (int i = 0; i < 32; i++) {
            int k2 = g_idx2[b * OC + o * 32 + i];
            c[g_pair[k2 * CH + o]]++;
        }
    }
    __syncthreads();
    for (int m = threadIdx.x; m < NF; m += 256) g_cnt[(long)bo * NF + m] = c[m];
}

// ---------------- A[bg][m] = sum_o qpw2[g*32+o] * cnt[b][o][m] ----------------
__global__ void A_kernel() {
    int bg = blockIdx.x;
    int b = bg >> 5, g = bg & 31;
    __shared__ float w[32];
    if (threadIdx.x < 32) w[threadIdx.x] = g_qpw2[g * 32 + threadIdx.x];
    __syncthreads();
    for (int m = threadIdx.x; m < NF; m += 256) {
        float acc = 0.f;
#pragma unroll
        for (int o = 0; o < 32; o++)
            acc += w[o] * (float)g_cnt[((long)(b * 32 + o)) * NF + m];
        g_A[(long)bg * NF + m] = acc;
    }
}

extern "C" void kernel_launch(void* const* d_in, const int* in_sizes, int n_in,
                              void* d_out, int out_size) {
    const float* x       = (const float*)d_in[0];
    const float* dw_w1   = (const float*)d_in[1];
    const float* pw_w1   = (const float*)d_in[2];
    const float* dw_w2   = (const float*)d_in[3];
    const float* pw_w2   = (const float*)d_in[4];
    const float* cb_dw   = (const float*)d_in[5];
    const float* cb_pw   = (const float*)d_in[6];
    const float* cb_dw2  = (const float*)d_in[7];
    const float* cb_pw2  = (const float*)d_in[8];
    const float* cb_fdw  = (const float*)d_in[9];
    const float* cb_fpw  = (const float*)d_in[10];
    const float* cb_fdw2 = (const float*)d_in[11];
    const float* cb_fpw2 = (const float*)d_in[12];
    const float* gamma   = (const float*)d_in[13];
    const float* beta    = (const float*)d_in[14];
    const float* rmean   = (const float*)d_in[15];
    const float* rvar    = (const float*)d_in[16];
    float* out = (float*)d_out;

    float *pSp, *pCs, *pA;
    cudaGetSymbolAddress((void**)&pSp, g_Sp);
    cudaGetSymbolAddress((void**)&pCs, g_Cs);
    cudaGetSymbolAddress((void**)&pA, g_A);

    static cudaStream_t s1 = [] { cudaStream_t s; cudaStreamCreateWithFlags(&s, cudaStreamNonBlocking); return s; }();
    static cudaEvent_t eFork = [] { cudaEvent_t e; cudaEventCreateWithFlags(&e, cudaEventDisableTiming); return e; }();
    static cudaEvent_t ePrep = [] { cudaEvent_t e; cudaEventCreateWithFlags(&e, cudaEventDisableTiming); return e; }();
    static cudaEvent_t eDot  = [] { cudaEvent_t e; cudaEventCreateWithFlags(&e, cudaEventDisableTiming); return e; }();
    static cudaEvent_t ePair = [] { cudaEvent_t e; cudaEventCreateWithFlags(&e, cudaEventDisableTiming); return e; }();

    cudaEventRecord(eFork, 0);
    cudaStreamWaitEvent(s1, eFork, 0);

    // aux chain: prep -> DOT1 (Sp[8..11]) -> G (18 slices, 288 blocks) -> pair
    prep_kernel<<<9 * NF + 4 * NF + 1, 256, 0, s1>>>(cb_fdw, cb_fpw, cb_fdw2, cb_fpw2,
                                                     dw_w1, pw_w1, dw_w2, pw_w2,
                                                     cb_dw, cb_pw, cb_dw2, cb_pw2);
    cudaEventRecord(ePrep, s1);
    gemm_dot1<<<dim3(4, 4, 4), 256, 0, s1>>>(cb_fpw, cb_fdw2);
    cudaEventRecord(eDot, s1);
    gemm_g<<<dim3(4, 4, 18), 256, 0, s1>>>(cb_fpw2);
    pair_kernel<<<NF, 256, 0, s1>>>();
    cudaEventRecord(ePair, s1);

    // main chain: VQ0 (128 blocks) -> am0 -> VQ1 -> am1 -> tail
    gemm_vq0<<<dim3(4, 4, 8), 256>>>(x, cb_fdw);
    cudaStreamWaitEvent(0, ePrep, 0);                        // norms + qw1
    am0_conv1<<<BI, 256>>>(pSp, cb_fdw);
    gemm_vq1<<<dim3(4, 4, 4), 256>>>(cb_fpw);
    cudaStreamWaitEvent(0, eDot, 0);                         // DOT1 partials ready
    am1_idx2<<<BI, 256>>>(pSp, pSp + 8L * NN2);
    cudaStreamWaitEvent(0, ePair, 0);
    cnt_kernel<<<B_ * CH, 256>>>();
    A_kernel<<<BI, 256>>>();
    sgemm_nn_split<<<dim3(16, 4, 4), 256>>>(pA, cb_fpw2, pCs);
    bn_reduce<<<BI, 256>>>(pCs, out, gamma, beta, rmean, rvar);
}

// round 15
// speedup vs baseline: 1.0361x; 1.0361x over previous
#include <cuda_runtime.h>

#define LEAK   0.1f
#define BN_EPS 1e-5f

// problem dims
#define B_   16
#define CH   32
#define H0c  48
#define H2c  46
#define H3c  44
#define D0   2304
#define D1   2116
#define D2   1936
#define NF   512
#define BI   512
#define OC   1024
#define BOC  16384
#define NN2  (NF * NF)
#define OSL  (512 * D2)

// ---------------- scratch ----------------
__device__ float g_Sp[12 * NN2];        // VQ0 [0:4) (VQ1 reuses); DOT1 [8:12)
__device__ float g_G[9 * NN2];          // G (full-K)
__device__ float g_h1[BI * D1];
__device__ float g_Cs[9 * NF * D2];     // shifted cb_fdw2; later reused for out partials (2 slices)
__device__ float g_A[BI * NF];
__device__ int   g_cnt[B_ * CH * NF];
__device__ int   g_idx2[BOC];
__device__ int   g_pair[NF * CH];
__device__ float g_qw1[CH * 9];
__device__ float g_qw2[CH * 9];
__device__ float g_qpw1[OC];
__device__ float g_qpw2[OC];
__device__ float g_nfdw[NF];
__device__ float g_nfpw[NF];
__device__ float g_nfdw2[NF];
__device__ float g_nfpw2[NF];

// ---------------- packed fp32x2 helpers ----------------
#define FMA2(acc, a, b) asm("fma.rn.f32x2 %0, %1, %2, %0;" : "+l"(acc) : "l"(a), "l"(b))
#define DUP2(d, x) asm("mov.b64 %0, {%1, %1};" : "=l"(d) : "r"(__float_as_uint(x)))

// ================= prepA: norms + weight VQ (small; unblocks am0) =================
__global__ void prepA_kernel(const float* __restrict__ cb_fdw, const float* __restrict__ cb_fpw,
                             const float* __restrict__ cb_fdw2, const float* __restrict__ cb_fpw2,
                             const float* __restrict__ dw1, const float* __restrict__ pw1,
                             const float* __restrict__ dw2, const float* __restrict__ pw2,
                             const float* __restrict__ cdw, const float* __restrict__ cpw,
                             const float* __restrict__ cdw2, const float* __restrict__ cpw2) {
    int b = blockIdx.x;
    if (b < 4 * NF) {
        int row = b & (NF - 1), which = b >> 9;
        const float* src; int D; float* dst;
        if (which == 0)      { src = cb_fdw;  D = D0; dst = g_nfdw;  }
        else if (which == 1) { src = cb_fpw;  D = D1; dst = g_nfpw;  }
        else if (which == 2) { src = cb_fdw2; D = D1; dst = g_nfdw2; }
        else                 { src = cb_fpw2; D = D2; dst = g_nfpw2; }
        const float* p = src + (long)row * D;
        float s = 0.f;
        for (int i = threadIdx.x; i < D; i += 256) { float v = p[i]; s += v * v; }
        __shared__ float sm[256];
        sm[threadIdx.x] = s; __syncthreads();
        for (int o = 128; o > 0; o >>= 1) {
            if (threadIdx.x < o) sm[threadIdx.x] += sm[threadIdx.x + o];
            __syncthreads();
        }
        if (threadIdx.x == 0) dst[row] = sm[0];
        return;
    }
    // weight VQ (one block)
    int t = threadIdx.x;
    if (t < 32) {
        float w[9];
        for (int j = 0; j < 9; j++) w[j] = dw1[t * 9 + j];
        float bd = 3.4e38f; int bk = 0;
        for (int k = 0; k < 256; k++) {
            float d = 0.f;
            for (int j = 0; j < 9; j++) { float e = w[j] - cdw[k * 9 + j]; d += e * e; }
            if (d < bd) { bd = d; bk = k; }
        }
        for (int j = 0; j < 9; j++) g_qw1[t * 9 + j] = cdw[bk * 9 + j];
        for (int j = 0; j < 9; j++) w[j] = dw2[t * 9 + j];
        bd = 3.4e38f; bk = 0;
        for (int k = 0; k < 256; k++) {
            float d = 0.f;
            for (int j = 0; j < 9; j++) { float e = w[j] - cdw2[k * 9 + j]; d += e * e; }
            if (d < bd) { bd = d; bk = k; }
        }
        for (int j = 0; j < 9; j++) g_qw2[t * 9 + j] = cdw2[bk * 9 + j];
    }
    for (int c = t; c < OC; c += 256) {
        float w = pw1[c]; float bd = 3.4e38f; int bk = 0;
        for (int k = 0; k < 256; k++) { float e = w - cpw[k]; float d = e * e; if (d < bd) { bd = d; bk = k; } }
        g_qpw1[c] = cpw[bk];
        w = pw2[c]; bd = 3.4e38f; bk = 0;
        for (int k = 0; k < 256; k++) { float e = w - cpw2[k]; float d = e * e; if (d < bd) { bd = d; bk = k; } }
        g_qpw2[c] = cpw2[bk];
    }
}

// ================= prepB: shifted cb_fdw2 copies (feeds G only) =================
__global__ void prepB_kernel(const float* __restrict__ cb_fdw2) {
    int b = blockIdx.x;
    int k = b & (NF - 1), t = b >> 9;
    int ty = t / 3, tx = t - ty * 3;
    const float* src = cb_fdw2 + (long)k * D1;
    float* dst = g_Cs + ((long)t * NF + k) * D2;
    for (int p = threadIdx.x; p < D2; p += 256) {
        int py = p / H3c, px = p - py * H3c;
        dst[p] = src[(py + ty) * H2c + px + tx];
    }
}

__device__ __forceinline__ float4 ld4_guard(const float* p, int k, int kend) {
    return (k < kend) ? *(const float4*)(p + k) : make_float4(0.f, 0.f, 0.f, 0.f);
}

// ================= NT GEMM core (R6 best): compact A, direct-u64 B, K-step 16 =================
__device__ __forceinline__ void nt_core(const float* __restrict__ A, const float* __restrict__ B,
                                        float* __restrict__ C, int ldk, int kb, int kend) {
    __shared__ float As[2][16][128];
    __shared__ float Bs[2][16][128];
    int tid = threadIdx.x;
    int m0 = blockIdx.y * 128, n0 = blockIdx.x * 128;
    int lr = tid >> 1, lc = (tid & 1) * 8;
    int tx = tid & 15, ty = tid >> 4;

    const float* Ab = A + (long)(m0 + lr) * ldk;
    const float* Bb = B + (long)(n0 + lr) * ldk;

    unsigned long long acc[8][4] = {};

    {
        float4 aL = ld4_guard(Ab, kb + lc, kend);
        float4 aH = ld4_guard(Ab, kb + lc + 4, kend);
        float4 bL = ld4_guard(Bb, kb + lc, kend);
        float4 bH = ld4_guard(Bb, kb + lc + 4, kend);
        As[0][lc + 0][lr] = aL.x; As[0][lc + 1][lr] = aL.y; As[0][lc + 2][lr] = aL.z; As[0][lc + 3][lr] = aL.w;
        As[0][lc + 4][lr] = aH.x; As[0][lc + 5][lr] = aH.y; As[0][lc + 6][lr] = aH.z; As[0][lc + 7][lr] = aH.w;
        Bs[0][lc + 0][lr] = bL.x; Bs[0][lc + 1][lr] = bL.y; Bs[0][lc + 2][lr] = bL.z; Bs[0][lc + 3][lr] = bL.w;
        Bs[0][lc + 4][lr] = bH.x; Bs[0][lc + 5][lr] = bH.y; Bs[0][lc + 6][lr] = bH.z; Bs[0][lc + 7][lr] = bH.w;
    }
    __syncthreads();

    int buf = 0;
    for (int k0 = kb; k0 < kend; k0 += 16) {
        bool nxt = (k0 + 16) < kend;
        float4 naL, naH, nbL, nbH;
        if (nxt) {
            naL = ld4_guard(Ab, k0 + 16 + lc, kend);
            naH = ld4_guard(Ab, k0 + 16 + lc + 4, kend);
            nbL = ld4_guard(Bb, k0 + 16 + lc, kend);
            nbH = ld4_guard(Bb, k0 + 16 + lc + 4, kend);
        }
#pragma unroll
        for (int kk = 0; kk < 16; kk++) {
            float4 a0 = *(const float4*)&As[buf][kk][ty * 4];
            float4 a1 = *(const float4*)&As[buf][kk][64 + ty * 4];
            ulonglong2 b01 = *(const ulonglong2*)&Bs[buf][kk][tx * 4];
            ulonglong2 b23 = *(const ulonglong2*)&Bs[buf][kk][64 + tx * 4];
            float ar[8] = { a0.x, a0.y, a0.z, a0.w, a1.x, a1.y, a1.z, a1.w };
#pragma unroll
            for (int i = 0; i < 8; i++) {
                unsigned long long ap; DUP2(ap, ar[i]);
                FMA2(acc[i][0], ap, b01.x); FMA2(acc[i][1], ap, b01.y);
                FMA2(acc[i][2], ap, b23.x); FMA2(acc[i][3], ap, b23.y);
            }
        }
        if (nxt) {
            int bN = buf ^ 1;
            As[bN][lc + 0][lr] = naL.x; As[bN][lc + 1][lr] = naL.y; As[bN][lc + 2][lr] = naL.z; As[bN][lc + 3][lr] = naL.w;
            As[bN][lc + 4][lr] = naH.x; As[bN][lc + 5][lr] = naH.y; As[bN][lc + 6][lr] = naH.z; As[bN][lc + 7][lr] = naH.w;
            Bs[bN][lc + 0][lr] = nbL.x; Bs[bN][lc + 1][lr] = nbL.y; Bs[bN][lc + 2][lr] = nbL.z; Bs[bN][lc + 3][lr] = nbL.w;
            Bs[bN][lc + 4][lr] = nbH.x; Bs[bN][lc + 5][lr] = nbH.y; Bs[bN][lc + 6][lr] = nbH.z; Bs[bN][lc + 7][lr] = nbH.w;
            __syncthreads();
            buf = bN;
        }
    }

#pragma unroll
    for (int i = 0; i < 8; i++) {
        int m = m0 + (i < 4 ? ty * 4 + i : 64 + ty * 4 + i - 4);
        float* Cr = C + (long)m * NF + n0;
        *(unsigned long long*)(Cr + tx * 4)          = acc[i][0];
        *(unsigned long long*)(Cr + tx * 4 + 2)      = acc[i][1];
        *(unsigned long long*)(Cr + 64 + tx * 4)     = acc[i][2];
        *(unsigned long long*)(Cr + 64 + tx * 4 + 2) = acc[i][3];
    }
}

// -------- VQ0: split-K 4 (z 0-3, chunk 576) -> Sp[0..3] --------
__global__ void __launch_bounds__(256) gemm_vq0(const float* __restrict__ x,
                                                const float* __restrict__ cbfdw) {
    int z = blockIdx.z;
    nt_core(x, cbfdw, g_Sp + (long)z * NN2, D0, z * 576, z * 576 + 576);
}

// -------- DOT1 (aux): split-K 4 -> Sp[8..11] --------
__global__ void __launch_bounds__(256) gemm_dot1(const float* __restrict__ cbfpw,
                                                 const float* __restrict__ cbfdw2) {
    int s = blockIdx.z;
    int kb = s * 532, kend = min(D1, kb + 532);
    nt_core(cbfpw, cbfdw2, g_Sp + (long)(8 + s) * NN2, D1, kb, kend);
}

// -------- VQ1 (main): split-K 4 -> Sp[0..3] (after am0 consumed VQ0) --------
__global__ void __launch_bounds__(256) gemm_vq1(const float* __restrict__ cbfpw) {
    int s = blockIdx.z;
    int kb = s * 532, kend = min(D1, kb + 532);
    nt_core(g_h1, cbfpw, g_Sp + (long)s * NN2, D1, kb, kend);
}

// -------- G: full-K, 9 z-slices (144 blocks, concurrent with main chain) --------
__global__ void __launch_bounds__(256) gemm_g(const float* __restrict__ cbfpw2) {
    int t = blockIdx.z;
    nt_core(g_Cs + (long)t * NF * D2, cbfpw2, g_G + (long)t * NN2, D2, 0, D2);
}

// -------- out GEMM: partial C = A (512x256 K-chunk) * B (512x1936), split-K 2 --------
__global__ void __launch_bounds__(256) sgemm_nn_split(
    const float* __restrict__ A, const float* __restrict__ B, float* __restrict__ C)
{
    const int N = D2, K = NF;
    int kb = blockIdx.z * 256, kend = kb + 256;
    C += (long)blockIdx.z * OSL;

    __shared__ float As[2][16][128];
    __shared__ float Bs[2][16][128];

    int tid = threadIdx.x;
    int m0 = blockIdx.y * 128, n0 = blockIdx.x * 128;
    int lr = tid >> 1, lc = (tid & 1) * 8;
    int krow = tid >> 4, nb_ = (tid & 15) * 8;
    int tx = tid & 15, ty = tid >> 4;

    const float* Ab = A + (long)(m0 + lr) * K;
    unsigned long long acc[8][4] = {};

    {
        float4 aL = *(const float4*)(Ab + kb + lc);
        float4 aH = *(const float4*)(Ab + kb + lc + 4);
        As[0][lc + 0][lr] = aL.x; As[0][lc + 1][lr] = aL.y; As[0][lc + 2][lr] = aL.z; As[0][lc + 3][lr] = aL.w;
        As[0][lc + 4][lr] = aH.x; As[0][lc + 5][lr] = aH.y; As[0][lc + 6][lr] = aH.z; As[0][lc + 7][lr] = aH.w;
        float4 bL = (n0 + nb_ < N) ? *(const float4*)(B + (long)(kb + krow) * N + n0 + nb_)
                                   : make_float4(0.f, 0.f, 0.f, 0.f);
        float4 bH = (n0 + nb_ + 4 < N) ? *(const float4*)(B + (long)(kb + krow) * N + n0 + nb_ + 4)
                                       : make_float4(0.f, 0.f, 0.f, 0.f);
        *(float4*)&Bs[0][krow][nb_] = bL;
        *(float4*)&Bs[0][krow][nb_ + 4] = bH;
    }
    __syncthreads();

    int buf = 0;
    for (int k0 = kb; k0 < kend; k0 += 16) {
        bool nxt = (k0 + 16) < kend;
        float4 naL, naH, nbL, nbH;
        if (nxt) {
            naL = *(const float4*)(Ab + k0 + 16 + lc);
            naH = *(const float4*)(Ab + k0 + 16 + lc + 4);
            nbL = (n0 + nb_ < N) ? *(const float4*)(B + (long)(k0 + 16 + krow) * N + n0 + nb_)
                                 : make_float4(0.f, 0.f, 0.f, 0.f);
            nbH = (n0 + nb_ + 4 < N) ? *(const float4*)(B + (long)(k0 + 16 + krow) * N + n0 + nb_ + 4)
                                     : make_float4(0.f, 0.f, 0.f, 0.f);
        }
#pragma unroll
        for (int kk = 0; kk < 16; kk++) {
            float4 a0 = *(const float4*)&As[buf][kk][ty * 4];
            float4 a1 = *(const float4*)&As[buf][kk][64 + ty * 4];
            ulonglong2 b01 = *(const ulonglong2*)&Bs[buf][kk][tx * 4];
            ulonglong2 b23 = *(const ulonglong2*)&Bs[buf][kk][64 + tx * 4];
            float ar[8] = { a0.x, a0.y, a0.z, a0.w, a1.x, a1.y, a1.z, a1.w };
#pragma unroll
            for (int i = 0; i < 8; i++) {
                unsigned long long ap; DUP2(ap, ar[i]);
                FMA2(acc[i][0], ap, b01.x); FMA2(acc[i][1], ap, b01.y);
                FMA2(acc[i][2], ap, b23.x); FMA2(acc[i][3], ap, b23.y);
            }
        }
        if (nxt) {
            int bN = buf ^ 1;
            As[bN][lc + 0][lr] = naL.x; As[bN][lc + 1][lr] = naL.y; As[bN][lc + 2][lr] = naL.z; As[bN][lc + 3][lr] = naL.w;
            As[bN][lc + 4][lr] = naH.x; As[bN][lc + 5][lr] = naH.y; As[bN][lc + 6][lr] = naH.z; As[bN][lc + 7][lr] = naH.w;
            *(float4*)&Bs[bN][krow][nb_] = nbL;
            *(float4*)&Bs[bN][krow][nb_ + 4] = nbH;
            __syncthreads();
            buf = bN;
        }
    }

#pragma unroll
    for (int i = 0; i < 8; i++) {
        int m = m0 + (i < 4 ? ty * 4 + i : 64 + ty * 4 + i - 4);
        float* Cr = C + (long)m * N;
#pragma unroll
        for (int jp = 0; jp < 4; jp++) {
            int n = n0 + (jp < 2 ? tx * 4 + jp * 2 : 64 + tx * 4 + (jp - 2) * 2);
            if (n < N) *(unsigned long long*)(Cr + n) = acc[i][jp];
        }
    }
}

// ---------------- BN + lrelu reduce of 2 out partials ----------------
__global__ void bn_reduce(const float* __restrict__ P, float* __restrict__ out,
                          const float* __restrict__ gamma, const float* __restrict__ beta,
                          const float* __restrict__ rmean, const float* __restrict__ rvar) {
    int m = blockIdx.x;
    int g = m & 31;
    float sc = rsqrtf(rvar[g] + BN_EPS) * gamma[g];
    float mu = rmean[g], bt = beta[g];
    const float* p0 = P + (long)m * D2;
    float* o = out + (long)m * D2;
    for (int n = threadIdx.x; n < D2; n += 256) {
        float v = p0[n] + p0[n + OSL];
        v = (v - mu) * sc + bt;
        o[n] = (v >= 0.f) ? v : LEAK * v;
    }
}

// ============ fused argmin(VQ0, 4 partials) + conv1 + lrelu ============
__global__ void am0_conv1(const float* __restrict__ Sp, const float* __restrict__ cb_fdw) {
    int v = blockIdx.x;
    int i = v & 31;
    __shared__ float sd[256]; __shared__ int si[256];
    __shared__ float w[9];
    __shared__ int s_idx;
    if (threadIdx.x < 9) w[threadIdx.x] = g_qw1[i * 9 + threadIdx.x];
    float bd = 3.4e38f; int bk = 0;
    for (int k = threadIdx.x; k < NF; k += 256) {
        float s = 0.f;
#pragma unroll
        for (int sp = 0; sp < 4; sp++)
            s += Sp[((long)sp * NF + v) * NF + k];
        float d = g_nfdw[k] - 2.0f * s;
        if (d < bd) { bd = d; bk = k; }
    }
    sd[threadIdx.x] = bd; si[threadIdx.x] = bk; __syncthreads();
    for (int o = 128; o > 0; o >>= 1) {
        if (threadIdx.x < o) {
            float d2 = sd[threadIdx.x + o]; int k2 = si[threadIdx.x + o];
            if (d2 < sd[threadIdx.x] || (d2 == sd[threadIdx.x] && k2 < si[threadIdx.x])) {
                sd[threadIdx.x] = d2; si[threadIdx.x] = k2;
            }
        }
        __syncthreads();
    }
    if (threadIdx.x == 0) s_idx = si[0];
    __syncthreads();
    const float* src = cb_fdw + (long)s_idx * D0;
    for (int p = threadIdx.x; p < D1; p += 256) {
        int py = p / H2c, px = p - py * H2c;
        const float* s0 = src + py * H0c + px;
        float acc = s0[0] * w[0] + s0[1] * w[1] + s0[2] * w[2]
                  + s0[H0c] * w[3] + s0[H0c + 1] * w[4] + s0[H0c + 2] * w[5]
                  + s0[2 * H0c] * w[6] + s0[2 * H0c + 1] * w[7] + s0[2 * H0c + 2] * w[8];
        g_h1[(long)v * D1 + p] = (acc >= 0.f) ? acc : LEAK * acc;
    }
}

// ============ fused argmin(VQ1, 4 partials) + idx2 scan (DOT 4 partials) ============
__global__ void am1_idx2(const float* __restrict__ Vp, const float* __restrict__ DOT) {
    int vbi = blockIdx.x;
    int b = vbi >> 5, i = vbi & 31;
    __shared__ float sd[256]; __shared__ int si[256];
    __shared__ int s_j;
    float bd = 3.4e38f; int bk = 0;
    for (int k = threadIdx.x; k < NF; k += 256) {
        float s = 0.f;
#pragma unroll
        for (int sp = 0; sp < 4; sp++)
            s += Vp[((long)sp * NF + vbi) * NF + k];
        float d = g_nfpw[k] - 2.0f * s;
        if (d < bd) { bd = d; bk = k; }
    }
    sd[threadIdx.x] = bd; si[threadIdx.x] = bk; __syncthreads();
    for (int o = 128; o > 0; o >>= 1) {
        if (threadIdx.x < o) {
            float d2 = sd[threadIdx.x + o]; int k2 = si[threadIdx.x + o];
            if (d2 < sd[threadIdx.x] || (d2 == sd[threadIdx.x] && k2 < si[threadIdx.x])) {
                sd[threadIdx.x] = d2; si[threadIdx.x] = k2;
            }
        }
        __syncthreads();
    }
    if (threadIdx.x == 0) s_j = si[0];
    __syncthreads();
    int j = s_j;
    __shared__ float dr[NF]; __shared__ float nn[NF];
    for (int k = threadIdx.x; k < NF; k += 256) {
        float v = 0.f;
#pragma unroll
        for (int sp = 0; sp < 4; sp++)
            v += DOT[((long)sp * NF + j) * NF + k];
        dr[k] = v;
        nn[k] = g_nfdw2[k];
    }
    __syncthreads();
    int warp = threadIdx.x >> 5, lane = threadIdx.x & 31;
    for (int o = warp; o < CH; o += 8) {
        float s = g_qpw1[o * 32 + i];
        float bd2 = 3.4e38f; int bk2 = 0;
        for (int k = lane; k < NF; k += 32) {
            float d = nn[k] - 2.0f * s * dr[k];
            if (d < bd2) { bd2 = d; bk2 = k; }
        }
        for (int off = 16; off > 0; off >>= 1) {
            float d2 = __shfl_down_sync(0xffffffffu, bd2, off);
            int k2 = __shfl_down_sync(0xffffffffu, bk2, off);
            if (d2 < bd2 || (d2 == bd2 && k2 < bk2)) { bd2 = d2; bk2 = k2; }
        }
        if (lane == 0) g_idx2[b * OC + o * 32 + i] = bk2;
    }
}

// ---------------- pair argmin over m per (k,o), single G slice ----------------
__global__ void __launch_bounds__(256) pair_kernel() {
    int k = blockIdx.x;
    __shared__ float gs[9][NF];
    __shared__ float nn[NF];
    __shared__ float ws[CH * 9];
    for (int t = 0; t < 9; t++)
        for (int m = threadIdx.x; m < NF; m += 256)
            gs[t][m] = g_G[((long)t * NF + k) * NF + m];
    for (int i = threadIdx.x; i < CH * 9; i += 256) ws[i] = g_qw2[i];
    for (int m = threadIdx.x; m < NF; m += 256) nn[m] = g_nfpw2[m];
    __syncthreads();
    int warp = threadIdx.x >> 5, lane = threadIdx.x & 31;
    for (int o = warp; o < CH; o += 8) {
        float wv[9];
#pragma unroll
        for (int t = 0; t < 9; t++) wv[t] = ws[o * 9 + t];
        float bd = 3.4e38f; int bk = 0;
        for (int m = lane; m < NF; m += 32) {
            float T = 0.f;
#pragma unroll
            for (int t = 0; t < 9; t++) T += wv[t] * gs[t][m];
            float d = nn[m] - 2.0f * T;
            if (d < bd) { bd = d; bk = m; }
        }
        for (int off = 16; off > 0; off >>= 1) {
            float d2 = __shfl_down_sync(0xffffffffu, bd, off);
            int k2 = __shfl_down_sync(0xffffffffu, bk, off);
            if (d2 < bd || (d2 == bd && k2 < bk)) { bd = d2; bk = k2; }
        }
        if (lane == 0) g_pair[k * CH + o] = bk;
    }
}

// ---------------- histogram ----------------
__global__ void cnt_kernel() {
    int bo = blockIdx.x;
    __shared__ int c[NF];
    for (int m = threadIdx.x; m < NF; m += 256) c[m] = 0;
    __syncthreads();
    if (threadIdx.x == 0) {
        int b = bo >> 5, o = bo & 31;
        for (int i = 0; i < 32; i++) {
            int k2 = g_idx2[b * OC + o * 32 + i];
            c[g_pair[k2 * CH + o]]++;
        }
    }
    __syncthreads();
    for (int m = threadIdx.x; m < NF; m += 256) g_cnt[(long)bo * NF + m] = c[m];
}

// ---------------- A[bg][m] = sum_o qpw2[g*32+o] * cnt[b][o][m] ----------------
__global__ void A_kernel() {
    int bg = blockIdx.x;
    int b = bg >> 5, g = bg & 31;
    __shared__ float w[32];
    if (threadIdx.x < 32) w[threadIdx.x] = g_qpw2[g * 32 + threadIdx.x];
    __syncthreads();
    for (int m = threadIdx.x; m < NF; m += 256) {
        float acc = 0.f;
#pragma unroll
        for (int o = 0; o < 32; o++)
            acc += w[o] * (float)g_cnt[((long)(b * 32 + o)) * NF + m];
        g_A[(long)bg * NF + m] = acc;
    }
}

extern "C" void kernel_launch(void* const* d_in, const int* in_sizes, int n_in,
                              void* d_out, int out_size) {
    const float* x       = (const float*)d_in[0];
    const float* dw_w1   = (const float*)d_in[1];
    const float* pw_w1   = (const float*)d_in[2];
    const float* dw_w2   = (const float*)d_in[3];
    const float* pw_w2   = (const float*)d_in[4];
    const float* cb_dw   = (const float*)d_in[5];
    const float* cb_pw   = (const float*)d_in[6];
    const float* cb_dw2  = (const float*)d_in[7];
    const float* cb_pw2  = (const float*)d_in[8];
    const float* cb_fdw  = (const float*)d_in[9];
    const float* cb_fpw  = (const float*)d_in[10];
    const float* cb_fdw2 = (const float*)d_in[11];
    const float* cb_fpw2 = (const float*)d_in[12];
    const float* gamma   = (const float*)d_in[13];
    const float* beta    = (const float*)d_in[14];
    const float* rmean   = (const float*)d_in[15];
    const float* rvar    = (const float*)d_in[16];
    float* out = (float*)d_out;

    float *pSp, *pCs, *pA;
    cudaGetSymbolAddress((void**)&pSp, g_Sp);
    cudaGetSymbolAddress((void**)&pCs, g_Cs);
    cudaGetSymbolAddress((void**)&pA, g_A);

    static cudaStream_t s1 = [] { cudaStream_t s; cudaStreamCreateWithFlags(&s, cudaStreamNonBlocking); return s; }();
    static cudaEvent_t eFork  = [] { cudaEvent_t e; cudaEventCreateWithFlags(&e, cudaEventDisableTiming); return e; }();
    static cudaEvent_t ePrepA = [] { cudaEvent_t e; cudaEventCreateWithFlags(&e, cudaEventDisableTiming); return e; }();
    static cudaEvent_t eDot   = [] { cudaEvent_t e; cudaEventCreateWithFlags(&e, cudaEventDisableTiming); return e; }();
    static cudaEvent_t ePair  = [] { cudaEvent_t e; cudaEventCreateWithFlags(&e, cudaEventDisableTiming); return e; }();

    cudaEventRecord(eFork, 0);
    cudaStreamWaitEvent(s1, eFork, 0);

    // aux chain: prepA (norms+quantw) -> DOT1 -> prepB (Cs shift) -> G -> pair
    prepA_kernel<<<4 * NF + 1, 256, 0, s1>>>(cb_fdw, cb_fpw, cb_fdw2, cb_fpw2,
                                             dw_w1, pw_w1, dw_w2, pw_w2,
                                             cb_dw, cb_pw, cb_dw2, cb_pw2);
    cudaEventRecord(ePrepA, s1);
    gemm_dot1<<<dim3(4, 4, 4), 256, 0, s1>>>(cb_fpw, cb_fdw2);
    cudaEventRecord(eDot, s1);
    prepB_kernel<<<9 * NF, 256, 0, s1>>>(cb_fdw2);
    gemm_g<<<dim3(4, 4, 9), 256, 0, s1>>>(cb_fpw2);
    pair_kernel<<<NF, 256, 0, s1>>>();
    cudaEventRecord(ePair, s1);

    // main chain: VQ0 (co-runs with prepA+DOT1) -> am0 -> VQ1 -> am1 -> tail
    gemm_vq0<<<dim3(4, 4, 4), 256>>>(x, cb_fdw);
    cudaStreamWaitEvent(0, ePrepA, 0);                       // norms + qw1
    am0_conv1<<<BI, 256>>>(pSp, cb_fdw);
    gemm_vq1<<<dim3(4, 4, 4), 256>>>(cb_fpw);
    cudaStreamWaitEvent(0, eDot, 0);                         // DOT1 partials ready
    am1_idx2<<<BI, 256>>>(pSp, pSp + 8L * NN2);
    cudaStreamWaitEvent(0, ePair, 0);
    cnt_kernel<<<B_ * CH, 256>>>();
    A_kernel<<<BI, 256>>>();
    sgemm_nn_split<<<dim3(16, 4, 2), 256>>>(pA, cb_fpw2, pCs);
    bn_reduce<<<BI, 256>>>(pCs, out, gamma, beta, rmean, rvar);
}

// round 16
// speedup vs baseline: 1.1700x; 1.1293x over previous
#include <cuda_runtime.h>

#define LEAK   0.1f
#define BN_EPS 1e-5f

// problem dims
#define B_   16
#define CH   32
#define H0c  48
#define H2c  46
#define H3c  44
#define D0   2304
#define D1   2116
#define D2   1936
#define NF   512
#define BI   512
#define OC   1024
#define BOC  16384
#define NN2  (NF * NF)
#define OSL  (512 * D2)

// ---------------- scratch ----------------
__device__ float g_Sp[12 * NN2];        // VQ0/VQ1 [0:4); DOT1 [8:12)
__device__ float g_G[9 * NN2];          // G (full-K)
__device__ float g_h1[BI * D1];
__device__ float g_Cs[9 * NF * D2];     // shifted cb_fdw2; later reused for out partials (2 slices)
__device__ float g_A[BI * NF];
__device__ int   g_cnt[B_ * CH * NF];
__device__ int   g_idx2[BOC];
__device__ int   g_pair[NF * CH];
__device__ float g_qw1[CH * 9];
__device__ float g_qw2[CH * 9];
__device__ float g_qpw1[OC];
__device__ float g_qpw2[OC];
__device__ float g_nfdw[NF];
__device__ float g_nfpw[NF];
__device__ float g_nfdw2[NF];
__device__ float g_nfpw2[NF];

// ---------------- packed fp32x2 helpers ----------------
#define FMA2(acc, a, b) asm("fma.rn.f32x2 %0, %1, %2, %0;" : "+l"(acc) : "l"(a), "l"(b))
#define DUP2(d, x) asm("mov.b64 %0, {%1, %1};" : "=l"(d) : "r"(__float_as_uint(x)))

// ================= prepA: norms + weight VQ (small; unblocks am0 + pair) =================
__global__ void prepA_kernel(const float* __restrict__ cb_fdw, const float* __restrict__ cb_fpw,
                             const float* __restrict__ cb_fdw2, const float* __restrict__ cb_fpw2,
                             const float* __restrict__ dw1, const float* __restrict__ pw1,
                             const float* __restrict__ dw2, const float* __restrict__ pw2,
                             const float* __restrict__ cdw, const float* __restrict__ cpw,
                             const float* __restrict__ cdw2, const float* __restrict__ cpw2) {
    int b = blockIdx.x;
    if (b < 4 * NF) {
        int row = b & (NF - 1), which = b >> 9;
        const float* src; int D; float* dst;
        if (which == 0)      { src = cb_fdw;  D = D0; dst = g_nfdw;  }
        else if (which == 1) { src = cb_fpw;  D = D1; dst = g_nfpw;  }
        else if (which == 2) { src = cb_fdw2; D = D1; dst = g_nfdw2; }
        else                 { src = cb_fpw2; D = D2; dst = g_nfpw2; }
        const float* p = src + (long)row * D;
        float s = 0.f;
        for (int i = threadIdx.x; i < D; i += 256) { float v = p[i]; s += v * v; }
        __shared__ float sm[256];
        sm[threadIdx.x] = s; __syncthreads();
        for (int o = 128; o > 0; o >>= 1) {
            if (threadIdx.x < o) sm[threadIdx.x] += sm[threadIdx.x + o];
            __syncthreads();
        }
        if (threadIdx.x == 0) dst[row] = sm[0];
        return;
    }
    // weight VQ (one block)
    int t = threadIdx.x;
    if (t < 32) {
        float w[9];
        for (int j = 0; j < 9; j++) w[j] = dw1[t * 9 + j];
        float bd = 3.4e38f; int bk = 0;
        for (int k = 0; k < 256; k++) {
            float d = 0.f;
            for (int j = 0; j < 9; j++) { float e = w[j] - cdw[k * 9 + j]; d += e * e; }
            if (d < bd) { bd = d; bk = k; }
        }
        for (int j = 0; j < 9; j++) g_qw1[t * 9 + j] = cdw[bk * 9 + j];
        for (int j = 0; j < 9; j++) w[j] = dw2[t * 9 + j];
        bd = 3.4e38f; bk = 0;
        for (int k = 0; k < 256; k++) {
            float d = 0.f;
            for (int j = 0; j < 9; j++) { float e = w[j] - cdw2[k * 9 + j]; d += e * e; }
            if (d < bd) { bd = d; bk = k; }
        }
        for (int j = 0; j < 9; j++) g_qw2[t * 9 + j] = cdw2[bk * 9 + j];
    }
    for (int c = t; c < OC; c += 256) {
        float w = pw1[c]; float bd = 3.4e38f; int bk = 0;
        for (int k = 0; k < 256; k++) { float e = w - cpw[k]; float d = e * e; if (d < bd) { bd = d; bk = k; } }
        g_qpw1[c] = cpw[bk];
        w = pw2[c]; bd = 3.4e38f; bk = 0;
        for (int k = 0; k < 256; k++) { float e = w - cpw2[k]; float d = e * e; if (d < bd) { bd = d; bk = k; } }
        g_qpw2[c] = cpw2[bk];
    }
}

// ================= prepB: shifted cb_fdw2 copies (feeds G only) =================
__global__ void prepB_kernel(const float* __restrict__ cb_fdw2) {
    int b = blockIdx.x;
    int k = b & (NF - 1), t = b >> 9;
    int ty = t / 3, tx = t - ty * 3;
    const float* src = cb_fdw2 + (long)k * D1;
    float* dst = g_Cs + ((long)t * NF + k) * D2;
    for (int p = threadIdx.x; p < D2; p += 256) {
        int py = p / H3c, px = p - py * H3c;
        dst[p] = src[(py + ty) * H2c + px + tx];
    }
}

__device__ __forceinline__ float4 ld4_guard(const float* p, int k, int kend) {
    return (k < kend) ? *(const float4*)(p + k) : make_float4(0.f, 0.f, 0.f, 0.f);
}

// ================= NT GEMM core (R6 best): compact A, direct-u64 B, K-step 16 =================
__device__ __forceinline__ void nt_core(const float* __restrict__ A, const float* __restrict__ B,
                                        float* __restrict__ C, int ldk, int kb, int kend) {
    __shared__ float As[2][16][128];
    __shared__ float Bs[2][16][128];
    int tid = threadIdx.x;
    int m0 = blockIdx.y * 128, n0 = blockIdx.x * 128;
    int lr = tid >> 1, lc = (tid & 1) * 8;
    int tx = tid & 15, ty = tid >> 4;

    const float* Ab = A + (long)(m0 + lr) * ldk;
    const float* Bb = B + (long)(n0 + lr) * ldk;

    unsigned long long acc[8][4] = {};

    {
        float4 aL = ld4_guard(Ab, kb + lc, kend);
        float4 aH = ld4_guard(Ab, kb + lc + 4, kend);
        float4 bL = ld4_guard(Bb, kb + lc, kend);
        float4 bH = ld4_guard(Bb, kb + lc + 4, kend);
        As[0][lc + 0][lr] = aL.x; As[0][lc + 1][lr] = aL.y; As[0][lc + 2][lr] = aL.z; As[0][lc + 3][lr] = aL.w;
        As[0][lc + 4][lr] = aH.x; As[0][lc + 5][lr] = aH.y; As[0][lc + 6][lr] = aH.z; As[0][lc + 7][lr] = aH.w;
        Bs[0][lc + 0][lr] = bL.x; Bs[0][lc + 1][lr] = bL.y; Bs[0][lc + 2][lr] = bL.z; Bs[0][lc + 3][lr] = bL.w;
        Bs[0][lc + 4][lr] = bH.x; Bs[0][lc + 5][lr] = bH.y; Bs[0][lc + 6][lr] = bH.z; Bs[0][lc + 7][lr] = bH.w;
    }
    __syncthreads();

    int buf = 0;
    for (int k0 = kb; k0 < kend; k0 += 16) {
        bool nxt = (k0 + 16) < kend;
        float4 naL, naH, nbL, nbH;
        if (nxt) {
            naL = ld4_guard(Ab, k0 + 16 + lc, kend);
            naH = ld4_guard(Ab, k0 + 16 + lc + 4, kend);
            nbL = ld4_guard(Bb, k0 + 16 + lc, kend);
            nbH = ld4_guard(Bb, k0 + 16 + lc + 4, kend);
        }
#pragma unroll
        for (int kk = 0; kk < 16; kk++) {
            float4 a0 = *(const float4*)&As[buf][kk][ty * 4];
            float4 a1 = *(const float4*)&As[buf][kk][64 + ty * 4];
            ulonglong2 b01 = *(const ulonglong2*)&Bs[buf][kk][tx * 4];
            ulonglong2 b23 = *(const ulonglong2*)&Bs[buf][kk][64 + tx * 4];
            float ar[8] = { a0.x, a0.y, a0.z, a0.w, a1.x, a1.y, a1.z, a1.w };
#pragma unroll
            for (int i = 0; i < 8; i++) {
                unsigned long long ap; DUP2(ap, ar[i]);
                FMA2(acc[i][0], ap, b01.x); FMA2(acc[i][1], ap, b01.y);
                FMA2(acc[i][2], ap, b23.x); FMA2(acc[i][3], ap, b23.y);
            }
        }
        if (nxt) {
            int bN = buf ^ 1;
            As[bN][lc + 0][lr] = naL.x; As[bN][lc + 1][lr] = naL.y; As[bN][lc + 2][lr] = naL.z; As[bN][lc + 3][lr] = naL.w;
            As[bN][lc + 4][lr] = naH.x; As[bN][lc + 5][lr] = naH.y; As[bN][lc + 6][lr] = naH.z; As[bN][lc + 7][lr] = naH.w;
            Bs[bN][lc + 0][lr] = nbL.x; Bs[bN][lc + 1][lr] = nbL.y; Bs[bN][lc + 2][lr] = nbL.z; Bs[bN][lc + 3][lr] = nbL.w;
            Bs[bN][lc + 4][lr] = nbH.x; Bs[bN][lc + 5][lr] = nbH.y; Bs[bN][lc + 6][lr] = nbH.z; Bs[bN][lc + 7][lr] = nbH.w;
            __syncthreads();
            buf = bN;
        }
    }

#pragma unroll
    for (int i = 0; i < 8; i++) {
        int m = m0 + (i < 4 ? ty * 4 + i : 64 + ty * 4 + i - 4);
        float* Cr = C + (long)m * NF + n0;
        *(unsigned long long*)(Cr + tx * 4)          = acc[i][0];
        *(unsigned long long*)(Cr + tx * 4 + 2)      = acc[i][1];
        *(unsigned long long*)(Cr + 64 + tx * 4)     = acc[i][2];
        *(unsigned long long*)(Cr + 64 + tx * 4 + 2) = acc[i][3];
    }
}

// -------- VQ0: split-K 4 (z 0-3, chunk 576) -> Sp[0..3] --------
__global__ void __launch_bounds__(256) gemm_vq0(const float* __restrict__ x,
                                                const float* __restrict__ cbfdw) {
    int z = blockIdx.z;
    nt_core(x, cbfdw, g_Sp + (long)z * NN2, D0, z * 576, z * 576 + 576);
}

// -------- DOT1 (main, pre-am0): split-K 4 -> Sp[8..11] --------
__global__ void __launch_bounds__(256) gemm_dot1(const float* __restrict__ cbfpw,
                                                 const float* __restrict__ cbfdw2) {
    int s = blockIdx.z;
    int kb = s * 532, kend = min(D1, kb + 532);
    nt_core(cbfpw, cbfdw2, g_Sp + (long)(8 + s) * NN2, D1, kb, kend);
}

// -------- VQ1 (main): split-K 4 -> Sp[0..3] (after am0 consumed VQ0) --------
__global__ void __launch_bounds__(256) gemm_vq1(const float* __restrict__ cbfpw) {
    int s = blockIdx.z;
    int kb = s * 532, kend = min(D1, kb + 532);
    nt_core(g_h1, cbfpw, g_Sp + (long)s * NN2, D1, kb, kend);
}

// -------- G: full-K, 9 z-slices (144 blocks, starts immediately after prepB) --------
__global__ void __launch_bounds__(256) gemm_g(const float* __restrict__ cbfpw2) {
    int t = blockIdx.z;
    nt_core(g_Cs + (long)t * NF * D2, cbfpw2, g_G + (long)t * NN2, D2, 0, D2);
}

// -------- out GEMM: partial C = A (512x256 K-chunk) * B (512x1936), split-K 2 --------
__global__ void __launch_bounds__(256) sgemm_nn_split(
    const float* __restrict__ A, const float* __restrict__ B, float* __restrict__ C)
{
    const int N = D2, K = NF;
    int kb = blockIdx.z * 256, kend = kb + 256;
    C += (long)blockIdx.z * OSL;

    __shared__ float As[2][16][128];
    __shared__ float Bs[2][16][128];

    int tid = threadIdx.x;
    int m0 = blockIdx.y * 128, n0 = blockIdx.x * 128;
    int lr = tid >> 1, lc = (tid & 1) * 8;
    int krow = tid >> 4, nb_ = (tid & 15) * 8;
    int tx = tid & 15, ty = tid >> 4;

    const float* Ab = A + (long)(m0 + lr) * K;
    unsigned long long acc[8][4] = {};

    {
        float4 aL = *(const float4*)(Ab + kb + lc);
        float4 aH = *(const float4*)(Ab + kb + lc + 4);
        As[0][lc + 0][lr] = aL.x; As[0][lc + 1][lr] = aL.y; As[0][lc + 2][lr] = aL.z; As[0][lc + 3][lr] = aL.w;
        As[0][lc + 4][lr] = aH.x; As[0][lc + 5][lr] = aH.y; As[0][lc + 6][lr] = aH.z; As[0][lc + 7][lr] = aH.w;
        float4 bL = (n0 + nb_ < N) ? *(const float4*)(B + (long)(kb + krow) * N + n0 + nb_)
                                   : make_float4(0.f, 0.f, 0.f, 0.f);
        float4 bH = (n0 + nb_ + 4 < N) ? *(const float4*)(B + (long)(kb + krow) * N + n0 + nb_ + 4)
                                       : make_float4(0.f, 0.f, 0.f, 0.f);
        *(float4*)&Bs[0][krow][nb_] = bL;
        *(float4*)&Bs[0][krow][nb_ + 4] = bH;
    }
    __syncthreads();

    int buf = 0;
    for (int k0 = kb; k0 < kend; k0 += 16) {
        bool nxt = (k0 + 16) < kend;
        float4 naL, naH, nbL, nbH;
        if (nxt) {
            naL = *(const float4*)(Ab + k0 + 16 + lc);
            naH = *(const float4*)(Ab + k0 + 16 + lc + 4);
            nbL = (n0 + nb_ < N) ? *(const float4*)(B + (long)(k0 + 16 + krow) * N + n0 + nb_)
                                 : make_float4(0.f, 0.f, 0.f, 0.f);
            nbH = (n0 + nb_ + 4 < N) ? *(const float4*)(B + (long)(k0 + 16 + krow) * N + n0 + nb_ + 4)
                                     : make_float4(0.f, 0.f, 0.f, 0.f);
        }
#pragma unroll
        for (int kk = 0; kk < 16; kk++) {
            float4 a0 = *(const float4*)&As[buf][kk][ty * 4];
            float4 a1 = *(const float4*)&As[buf][kk][64 + ty * 4];
            ulonglong2 b01 = *(const ulonglong2*)&Bs[buf][kk][tx * 4];
            ulonglong2 b23 = *(const ulonglong2*)&Bs[buf][kk][64 + tx * 4];
            float ar[8] = { a0.x, a0.y, a0.z, a0.w, a1.x, a1.y, a1.z, a1.w };
#pragma unroll
            for (int i = 0; i < 8; i++) {
                unsigned long long ap; DUP2(ap, ar[i]);
                FMA2(acc[i][0], ap, b01.x); FMA2(acc[i][1], ap, b01.y);
                FMA2(acc[i][2], ap, b23.x); FMA2(acc[i][3], ap, b23.y);
            }
        }
        if (nxt) {
            int bN = buf ^ 1;
            As[bN][lc + 0][lr] = naL.x; As[bN][lc + 1][lr] = naL.y; As[bN][lc + 2][lr] = naL.z; As[bN][lc + 3][lr] = naL.w;
            As[bN][lc + 4][lr] = naH.x; As[bN][lc + 5][lr] = naH.y; As[bN][lc + 6][lr] = naH.z; As[bN][lc + 7][lr] = naH.w;
            *(float4*)&Bs[bN][krow][nb_] = nbL;
            *(float4*)&Bs[bN][krow][nb_ + 4] = nbH;
            __syncthreads();
            buf = bN;
        }
    }

#pragma unroll
    for (int i = 0; i < 8; i++) {
        int m = m0 + (i < 4 ? ty * 4 + i : 64 + ty * 4 + i - 4);
        float* Cr = C + (long)m * N;
#pragma unroll
        for (int jp = 0; jp < 4; jp++) {
            int n = n0 + (jp < 2 ? tx * 4 + jp * 2 : 64 + tx * 4 + (jp - 2) * 2);
            if (n < N) *(unsigned long long*)(Cr + n) = acc[i][jp];
        }
    }
}

// ---------------- BN + lrelu reduce of 2 out partials ----------------
__global__ void bn_reduce(const float* __restrict__ P, float* __restrict__ out,
                          const float* __restrict__ gamma, const float* __restrict__ beta,
                          const float* __restrict__ rmean, const float* __restrict__ rvar) {
    int m = blockIdx.x;
    int g = m & 31;
    float sc = rsqrtf(rvar[g] + BN_EPS) * gamma[g];
    float mu = rmean[g], bt = beta[g];
    const float* p0 = P + (long)m * D2;
    float* o = out + (long)m * D2;
    for (int n = threadIdx.x; n < D2; n += 256) {
        float v = p0[n] + p0[n + OSL];
        v = (v - mu) * sc + bt;
        o[n] = (v >= 0.f) ? v : LEAK * v;
    }
}

// ============ fused argmin(VQ0, 4 partials) + conv1 + lrelu ============
__global__ void am0_conv1(const float* __restrict__ Sp, const float* __restrict__ cb_fdw) {
    int v = blockIdx.x;
    int i = v & 31;
    __shared__ float sd[256]; __shared__ int si[256];
    __shared__ float w[9];
    __shared__ int s_idx;
    if (threadIdx.x < 9) w[threadIdx.x] = g_qw1[i * 9 + threadIdx.x];
    float bd = 3.4e38f; int bk = 0;
    for (int k = threadIdx.x; k < NF; k += 256) {
        float s = 0.f;
#pragma unroll
        for (int sp = 0; sp < 4; sp++)
            s += Sp[((long)sp * NF + v) * NF + k];
        float d = g_nfdw[k] - 2.0f * s;
        if (d < bd) { bd = d; bk = k; }
    }
    sd[threadIdx.x] = bd; si[threadIdx.x] = bk; __syncthreads();
    for (int o = 128; o > 0; o >>= 1) {
        if (threadIdx.x < o) {
            float d2 = sd[threadIdx.x + o]; int k2 = si[threadIdx.x + o];
            if (d2 < sd[threadIdx.x] || (d2 == sd[threadIdx.x] && k2 < si[threadIdx.x])) {
                sd[threadIdx.x] = d2; si[threadIdx.x] = k2;
            }
        }
        __syncthreads();
    }
    if (threadIdx.x == 0) s_idx = si[0];
    __syncthreads();
    const float* src = cb_fdw + (long)s_idx * D0;
    for (int p = threadIdx.x; p < D1; p += 256) {
        int py = p / H2c, px = p - py * H2c;
        const float* s0 = src + py * H0c + px;
        float acc = s0[0] * w[0] + s0[1] * w[1] + s0[2] * w[2]
                  + s0[H0c] * w[3] + s0[H0c + 1] * w[4] + s0[H0c + 2] * w[5]
                  + s0[2 * H0c] * w[6] + s0[2 * H0c + 1] * w[7] + s0[2 * H0c + 2] * w[8];
        g_h1[(long)v * D1 + p] = (acc >= 0.f) ? acc : LEAK * acc;
    }
}

// ============ fused argmin(VQ1, 4 partials) + idx2 scan (DOT 4 partials) ============
__global__ void am1_idx2(const float* __restrict__ Vp, const float* __restrict__ DOT) {
    int vbi = blockIdx.x;
    int b = vbi >> 5, i = vbi & 31;
    __shared__ float sd[256]; __shared__ int si[256];
    __shared__ int s_j;
    float bd = 3.4e38f; int bk = 0;
    for (int k = threadIdx.x; k < NF; k += 256) {
        float s = 0.f;
#pragma unroll
        for (int sp = 0; sp < 4; sp++)
            s += Vp[((long)sp * NF + vbi) * NF + k];
        float d = g_nfpw[k] - 2.0f * s;
        if (d < bd) { bd = d; bk = k; }
    }
    sd[threadIdx.x] = bd; si[threadIdx.x] = bk; __syncthreads();
    for (int o = 128; o > 0; o >>= 1) {
        if (threadIdx.x < o) {
            float d2 = sd[threadIdx.x + o]; int k2 = si[threadIdx.x + o];
            if (d2 < sd[threadIdx.x] || (d2 == sd[threadIdx.x] && k2 < si[threadIdx.x])) {
                sd[threadIdx.x] = d2; si[threadIdx.x] = k2;
            }
        }
        __syncthreads();
    }
    if (threadIdx.x == 0) s_j = si[0];
    __syncthreads();
    int j = s_j;
    __shared__ float dr[NF]; __shared__ float nn[NF];
    for (int k = threadIdx.x; k < NF; k += 256) {
        float v = 0.f;
#pragma unroll
        for (int sp = 0; sp < 4; sp++)
            v += DOT[((long)sp * NF + j) * NF + k];
        dr[k] = v;
        nn[k] = g_nfdw2[k];
    }
    __syncthreads();
    int warp = threadIdx.x >> 5, lane = threadIdx.x & 31;
    for (int o = warp; o < CH; o += 8) {
        float s = g_qpw1[o * 32 + i];
        float bd2 = 3.4e38f; int bk2 = 0;
        for (int k = lane; k < NF; k += 32) {
            float d = nn[k] - 2.0f * s * dr[k];
            if (d < bd2) { bd2 = d; bk2 = k; }
        }
        for (int off = 16; off > 0; off >>= 1) {
            float d2 = __shfl_down_sync(0xffffffffu, bd2, off);
            int k2 = __shfl_down_sync(0xffffffffu, bk2, off);
            if (d2 < bd2 || (d2 == bd2 && k2 < bk2)) { bd2 = d2; bk2 = k2; }
        }
        if (lane == 0) g_idx2[b * OC + o * 32 + i] = bk2;
    }
}

// ---------------- pair argmin over m per (k,o), single G slice ----------------
__global__ void __launch_bounds__(256) pair_kernel() {
    int k = blockIdx.x;
    __shared__ float gs[9][NF];
    __shared__ float nn[NF];
    __shared__ float ws[CH * 9];
    for (int t = 0; t < 9; t++)
        for (int m = threadIdx.x; m < NF; m += 256)
            gs[t][m] = g_G[((long)t * NF + k) * NF + m];
    for (int i = threadIdx.x; i < CH * 9; i += 256) ws[i] = g_qw2[i];
    for (int m = threadIdx.x; m < NF; m += 256) nn[m] = g_nfpw2[m];
    __syncthreads();
    int warp = threadIdx.x >> 5, lane = threadIdx.x & 31;
    for (int o = warp; o < CH; o += 8) {
        float wv[9];
#pragma unroll
        for (int t = 0; t < 9; t++) wv[t] = ws[o * 9 + t];
        float bd = 3.4e38f; int bk = 0;
        for (int m = lane; m < NF; m += 32) {
            float T = 0.f;
#pragma unroll
            for (int t = 0; t < 9; t++) T += wv[t] * gs[t][m];
            float d = nn[m] - 2.0f * T;
            if (d < bd) { bd = d; bk = m; }
        }
        for (int off = 16; off > 0; off >>= 1) {
            float d2 = __shfl_down_sync(0xffffffffu, bd, off);
            int k2 = __shfl_down_sync(0xffffffffu, bk, off);
            if (d2 < bd || (d2 == bd && k2 < bk)) { bd = d2; bk = k2; }
        }
        if (lane == 0) g_pair[k * CH + o] = bk;
    }
}

// ---------------- histogram ----------------
__global__ void cnt_kernel() {
    int bo = blockIdx.x;
    __shared__ int c[NF];
    for (int m = threadIdx.x; m < NF; m += 256) c[m] = 0;
    __syncthreads();
    if (threadIdx.x == 0) {
        int b = bo >> 5, o = bo & 31;
        for (int i = 0; i < 32; i++) {
            int k2 = g_idx2[b * OC + o * 32 + i];
            c[g_pair[k2 * CH + o]]++;
        }
    }
    __syncthreads();
    for (int m = threadIdx.x; m < NF; m += 256) g_cnt[(long)bo * NF + m] = c[m];
}

// ---------------- A[bg][m] = sum_o qpw2[g*32+o] * cnt[b][o][m] ----------------
__global__ void A_kernel() {
    int bg = blockIdx.x;
    int b = bg >> 5, g = bg & 31;
    __shared__ float w[32];
    if (threadIdx.x < 32) w[threadIdx.x] = g_qpw2[g * 32 + threadIdx.x];
    __syncthreads();
    for (int m = threadIdx.x; m < NF; m += 256) {
        float acc = 0.f;
#pragma unroll
        for (int o = 0; o < 32; o++)
            acc += w[o] * (float)g_cnt[((long)(b * 32 + o)) * NF + m];
        g_A[(long)bg * NF + m] = acc;
    }
}

extern "C" void kernel_launch(void* const* d_in, const int* in_sizes, int n_in,
                              void* d_out, int out_size) {
    const float* x       = (const float*)d_in[0];
    const float* dw_w1   = (const float*)d_in[1];
    const float* pw_w1   = (const float*)d_in[2];
    const float* dw_w2   = (const float*)d_in[3];
    const float* pw_w2   = (const float*)d_in[4];
    const float* cb_dw   = (const float*)d_in[5];
    const float* cb_pw   = (const float*)d_in[6];
    const float* cb_dw2  = (const float*)d_in[7];
    const float* cb_pw2  = (const float*)d_in[8];
    const float* cb_fdw  = (const float*)d_in[9];
    const float* cb_fpw  = (const float*)d_in[10];
    const float* cb_fdw2 = (const float*)d_in[11];
    const float* cb_fpw2 = (const float*)d_in[12];
    const float* gamma   = (const float*)d_in[13];
    const float* beta    = (const float*)d_in[14];
    const float* rmean   = (const float*)d_in[15];
    const float* rvar    = (const float*)d_in[16];
    float* out = (float*)d_out;

    float *pSp, *pCs, *pA;
    cudaGetSymbolAddress((void**)&pSp, g_Sp);
    cudaGetSymbolAddress((void**)&pCs, g_Cs);
    cudaGetSymbolAddress((void**)&pA, g_A);

    static cudaStream_t s1 = [] { cudaStream_t s; cudaStreamCreateWithFlags(&s, cudaStreamNonBlocking); return s; }();
    static cudaEvent_t eFork  = [] { cudaEvent_t e; cudaEventCreateWithFlags(&e, cudaEventDisableTiming); return e; }();
    static cudaEvent_t ePrepA = [] { cudaEvent_t e; cudaEventCreateWithFlags(&e, cudaEventDisableTiming); return e; }();
    static cudaEvent_t ePair  = [] { cudaEvent_t e; cudaEventCreateWithFlags(&e, cudaEventDisableTiming); return e; }();

    cudaEventRecord(eFork, 0);
    cudaStreamWaitEvent(s1, eFork, 0);

    // aux chain: prepB (Cs shift) -> G  [starts immediately]
    prepB_kernel<<<9 * NF, 256, 0, s1>>>(cb_fdw2);
    gemm_g<<<dim3(4, 4, 9), 256, 0, s1>>>(cb_fpw2);

    // main: prepA first (tiny), then VQ0 + DOT1 co-run with aux's prepB/G
    prepA_kernel<<<4 * NF + 1, 256>>>(cb_fdw, cb_fpw, cb_fdw2, cb_fpw2,
                                      dw_w1, pw_w1, dw_w2, pw_w2,
                                      cb_dw, cb_pw, cb_dw2, cb_pw2);
    cudaEventRecord(ePrepA, 0);

    // aux: pair needs qw2/nfpw2 from prepA
    cudaStreamWaitEvent(s1, ePrepA, 0);
    pair_kernel<<<NF, 256, 0, s1>>>();
    cudaEventRecord(ePair, s1);

    // main chain continues
    gemm_vq0<<<dim3(4, 4, 4), 256>>>(x, cb_fdw);
    gemm_dot1<<<dim3(4, 4, 4), 256>>>(cb_fpw, cb_fdw2);
    am0_conv1<<<BI, 256>>>(pSp, cb_fdw);
    gemm_vq1<<<dim3(4, 4, 4), 256>>>(cb_fpw);
    am1_idx2<<<BI, 256>>>(pSp, pSp + 8L * NN2);
    cudaStreamWaitEvent(0, ePair, 0);
    cnt_kernel<<<B_ * CH, 256>>>();
    A_kernel<<<BI, 256>>>();
    sgemm_nn_split<<<dim3(16, 4, 2), 256>>>(pA, cb_fpw2, pCs);
    bn_reduce<<<BI, 256>>>(pCs, out, gamma, beta, rmean, rvar);
}

// round 17
// speedup vs baseline: 1.1701x; 1.0001x over previous
#include <cuda_runtime.h>

#define LEAK   0.1f
#define BN_EPS 1e-5f

// problem dims
#define B_   16
#define CH   32
#define H0c  48
#define H2c  46
#define H3c  44
#define D0   2304
#define D1   2116
#define D2   1936
#define NF   512
#define BI   512
#define OC   1024
#define BOC  16384
#define NN2  (NF * NF)
#define OSL  (512 * D2)

// ---------------- scratch ----------------
__device__ float g_Sp[12 * NN2];        // VQ0/VQ1 [0:4); DOT1 [8:12)
__device__ float g_G[9 * NN2];          // G (full-K)
__device__ float g_h1[BI * D1];
__device__ float g_Cs[9 * NF * D2];     // shifted cb_fdw2; later reused for out partials (2 slices)
__device__ float g_A[BI * NF];
__device__ int   g_cnt[B_ * CH * NF];
__device__ int   g_idx2[BOC];
__device__ int   g_pair[NF * CH];
__device__ float g_qw1[CH * 9];
__device__ float g_qw2[CH * 9];
__device__ float g_qpw1[OC];
__device__ float g_qpw2[OC];
__device__ float g_nfdw[NF];
__device__ float g_nfpw[NF];
__device__ float g_nfdw2[NF];
__device__ float g_nfpw2[NF];

// ---------------- packed fp32x2 helpers ----------------
#define FMA2(acc, a, b) asm("fma.rn.f32x2 %0, %1, %2, %0;" : "+l"(acc) : "l"(a), "l"(b))
#define DUP2(d, x) asm("mov.b64 %0, {%1, %1};" : "=l"(d) : "r"(__float_as_uint(x)))

// ================= prepA: norms + weight VQ (small; unblocks am0 + pair) =================
__global__ void prepA_kernel(const float* __restrict__ cb_fdw, const float* __restrict__ cb_fpw,
                             const float* __restrict__ cb_fdw2, const float* __restrict__ cb_fpw2,
                             const float* __restrict__ dw1, const float* __restrict__ pw1,
                             const float* __restrict__ dw2, const float* __restrict__ pw2,
                             const float* __restrict__ cdw, const float* __restrict__ cpw,
                             const float* __restrict__ cdw2, const float* __restrict__ cpw2) {
    int b = blockIdx.x;
    if (b < 4 * NF) {
        int row = b & (NF - 1), which = b >> 9;
        const float* src; int D; float* dst;
        if (which == 0)      { src = cb_fdw;  D = D0; dst = g_nfdw;  }
        else if (which == 1) { src = cb_fpw;  D = D1; dst = g_nfpw;  }
        else if (which == 2) { src = cb_fdw2; D = D1; dst = g_nfdw2; }
        else                 { src = cb_fpw2; D = D2; dst = g_nfpw2; }
        const float* p = src + (long)row * D;
        float s = 0.f;
        for (int i = threadIdx.x; i < D; i += 256) { float v = p[i]; s += v * v; }
        __shared__ float sm[256];
        sm[threadIdx.x] = s; __syncthreads();
        for (int o = 128; o > 0; o >>= 1) {
            if (threadIdx.x < o) sm[threadIdx.x] += sm[threadIdx.x + o];
            __syncthreads();
        }
        if (threadIdx.x == 0) dst[row] = sm[0];
        return;
    }
    // weight VQ (one block)
    int t = threadIdx.x;
    if (t < 32) {
        float w[9];
        for (int j = 0; j < 9; j++) w[j] = dw1[t * 9 + j];
        float bd = 3.4e38f; int bk = 0;
        for (int k = 0; k < 256; k++) {
            float d = 0.f;
            for (int j = 0; j < 9; j++) { float e = w[j] - cdw[k * 9 + j]; d += e * e; }
            if (d < bd) { bd = d; bk = k; }
        }
        for (int j = 0; j < 9; j++) g_qw1[t * 9 + j] = cdw[bk * 9 + j];
        for (int j = 0; j < 9; j++) w[j] = dw2[t * 9 + j];
        bd = 3.4e38f; bk = 0;
        for (int k = 0; k < 256; k++) {
            float d = 0.f;
            for (int j = 0; j < 9; j++) { float e = w[j] - cdw2[k * 9 + j]; d += e * e; }
            if (d < bd) { bd = d; bk = k; }
        }
        for (int j = 0; j < 9; j++) g_qw2[t * 9 + j] = cdw2[bk * 9 + j];
    }
    for (int c = t; c < OC; c += 256) {
        float w = pw1[c]; float bd = 3.4e38f; int bk = 0;
        for (int k = 0; k < 256; k++) { float e = w - cpw[k]; float d = e * e; if (d < bd) { bd = d; bk = k; } }
        g_qpw1[c] = cpw[bk];
        w = pw2[c]; bd = 3.4e38f; bk = 0;
        for (int k = 0; k < 256; k++) { float e = w - cpw2[k]; float d = e * e; if (d < bd) { bd = d; bk = k; } }
        g_qpw2[c] = cpw2[bk];
    }
}

// ================= prepB: shifted cb_fdw2 copies (feeds G only) =================
__global__ void prepB_kernel(const float* __restrict__ cb_fdw2) {
    int b = blockIdx.x;
    int k = b & (NF - 1), t = b >> 9;
    int ty = t / 3, tx = t - ty * 3;
    const float* src = cb_fdw2 + (long)k * D1;
    float* dst = g_Cs + ((long)t * NF + k) * D2;
    for (int p = threadIdx.x; p < D2; p += 256) {
        int py = p / H3c, px = p - py * H3c;
        dst[p] = src[(py + ty) * H2c + px + tx];
    }
}

__device__ __forceinline__ float4 ld4_guard(const float* p, int k, int kend) {
    return (k < kend) ? *(const float4*)(p + k) : make_float4(0.f, 0.f, 0.f, 0.f);
}

// ================= NT GEMM core (R6 best): compact A, direct-u64 B, K-step 16 =================
__device__ __forceinline__ void nt_core(const float* __restrict__ A, const float* __restrict__ B,
                                        float* __restrict__ C, int ldk, int kb, int kend) {
    __shared__ float As[2][16][128];
    __shared__ float Bs[2][16][128];
    int tid = threadIdx.x;
    int m0 = blockIdx.y * 128, n0 = blockIdx.x * 128;
    int lr = tid >> 1, lc = (tid & 1) * 8;
    int tx = tid & 15, ty = tid >> 4;

    const float* Ab = A + (long)(m0 + lr) * ldk;
    const float* Bb = B + (long)(n0 + lr) * ldk;

    unsigned long long acc[8][4] = {};

    {
        float4 aL = ld4_guard(Ab, kb + lc, kend);
        float4 aH = ld4_guard(Ab, kb + lc + 4, kend);
        float4 bL = ld4_guard(Bb, kb + lc, kend);
        float4 bH = ld4_guard(Bb, kb + lc + 4, kend);
        As[0][lc + 0][lr] = aL.x; As[0][lc + 1][lr] = aL.y; As[0][lc + 2][lr] = aL.z; As[0][lc + 3][lr] = aL.w;
        As[0][lc + 4][lr] = aH.x; As[0][lc + 5][lr] = aH.y; As[0][lc + 6][lr] = aH.z; As[0][lc + 7][lr] = aH.w;
        Bs[0][lc + 0][lr] = bL.x; Bs[0][lc + 1][lr] = bL.y; Bs[0][lc + 2][lr] = bL.z; Bs[0][lc + 3][lr] = bL.w;
        Bs[0][lc + 4][lr] = bH.x; Bs[0][lc + 5][lr] = bH.y; Bs[0][lc + 6][lr] = bH.z; Bs[0][lc + 7][lr] = bH.w;
    }
    __syncthreads();

    int buf = 0;
    for (int k0 = kb; k0 < kend; k0 += 16) {
        bool nxt = (k0 + 16) < kend;
        float4 naL, naH, nbL, nbH;
        if (nxt) {
            naL = ld4_guard(Ab, k0 + 16 + lc, kend);
            naH = ld4_guard(Ab, k0 + 16 + lc + 4, kend);
            nbL = ld4_guard(Bb, k0 + 16 + lc, kend);
            nbH = ld4_guard(Bb, k0 + 16 + lc + 4, kend);
        }
#pragma unroll
        for (int kk = 0; kk < 16; kk++) {
            float4 a0 = *(const float4*)&As[buf][kk][ty * 4];
            float4 a1 = *(const float4*)&As[buf][kk][64 + ty * 4];
            ulonglong2 b01 = *(const ulonglong2*)&Bs[buf][kk][tx * 4];
            ulonglong2 b23 = *(const ulonglong2*)&Bs[buf][kk][64 + tx * 4];
            float ar[8] = { a0.x, a0.y, a0.z, a0.w, a1.x, a1.y, a1.z, a1.w };
#pragma unroll
            for (int i = 0; i < 8; i++) {
                unsigned long long ap; DUP2(ap, ar[i]);
                FMA2(acc[i][0], ap, b01.x); FMA2(acc[i][1], ap, b01.y);
                FMA2(acc[i][2], ap, b23.x); FMA2(acc[i][3], ap, b23.y);
            }
        }
        if (nxt) {
            int bN = buf ^ 1;
            As[bN][lc + 0][lr] = naL.x; As[bN][lc + 1][lr] = naL.y; As[bN][lc + 2][lr] = naL.z; As[bN][lc + 3][lr] = naL.w;
            As[bN][lc + 4][lr] = naH.x; As[bN][lc + 5][lr] = naH.y; As[bN][lc + 6][lr] = naH.z; As[bN][lc + 7][lr] = naH.w;
            Bs[bN][lc + 0][lr] = nbL.x; Bs[bN][lc + 1][lr] = nbL.y; Bs[bN][lc + 2][lr] = nbL.z; Bs[bN][lc + 3][lr] = nbL.w;
            Bs[bN][lc + 4][lr] = nbH.x; Bs[bN][lc + 5][lr] = nbH.y; Bs[bN][lc + 6][lr] = nbH.z; Bs[bN][lc + 7][lr] = nbH.w;
            __syncthreads();
            buf = bN;
        }
    }

#pragma unroll
    for (int i = 0; i < 8; i++) {
        int m = m0 + (i < 4 ? ty * 4 + i : 64 + ty * 4 + i - 4);
        float* Cr = C + (long)m * NF + n0;
        *(unsigned long long*)(Cr + tx * 4)          = acc[i][0];
        *(unsigned long long*)(Cr + tx * 4 + 2)      = acc[i][1];
        *(unsigned long long*)(Cr + 64 + tx * 4)     = acc[i][2];
        *(unsigned long long*)(Cr + 64 + tx * 4 + 2) = acc[i][3];
    }
}

// -------- VQ0: split-K 4 (z 0-3, chunk 576) -> Sp[0..3] --------
__global__ void __launch_bounds__(256) gemm_vq0(const float* __restrict__ x,
                                                const float* __restrict__ cbfdw) {
    int z = blockIdx.z;
    nt_core(x, cbfdw, g_Sp + (long)z * NN2, D0, z * 576, z * 576 + 576);
}

// -------- DOT1 (main, pre-am0): split-K 4 -> Sp[8..11] --------
__global__ void __launch_bounds__(256) gemm_dot1(const float* __restrict__ cbfpw,
                                                 const float* __restrict__ cbfdw2) {
    int s = blockIdx.z;
    int kb = s * 532, kend = min(D1, kb + 532);
    nt_core(cbfpw, cbfdw2, g_Sp + (long)(8 + s) * NN2, D1, kb, kend);
}

// -------- VQ1 (main): split-K 4 -> Sp[0..3] (after am0 consumed VQ0) --------
__global__ void __launch_bounds__(256) gemm_vq1(const float* __restrict__ cbfpw) {
    int s = blockIdx.z;
    int kb = s * 532, kend = min(D1, kb + 532);
    nt_core(g_h1, cbfpw, g_Sp + (long)s * NN2, D1, kb, kend);
}

// -------- G: full-K, 9 z-slices (144 blocks, starts immediately after prepB) --------
__global__ void __launch_bounds__(256) gemm_g(const float* __restrict__ cbfpw2) {
    int t = blockIdx.z;
    nt_core(g_Cs + (long)t * NF * D2, cbfpw2, g_G + (long)t * NN2, D2, 0, D2);
}

// -------- out GEMM: partial C = A (512x256 K-chunk) * B (512x1936), split-K 2 --------
__global__ void __launch_bounds__(256) sgemm_nn_split(
    const float* __restrict__ A, const float* __restrict__ B, float* __restrict__ C)
{
    const int N = D2, K = NF;
    int kb = blockIdx.z * 256, kend = kb + 256;
    C += (long)blockIdx.z * OSL;

    __shared__ float As[2][16][128];
    __shared__ float Bs[2][16][128];

    int tid = threadIdx.x;
    int m0 = blockIdx.y * 128, n0 = blockIdx.x * 128;
    int lr = tid >> 1, lc = (tid & 1) * 8;
    int krow = tid >> 4, nb_ = (tid & 15) * 8;
    int tx = tid & 15, ty = tid >> 4;

    const float* Ab = A + (long)(m0 + lr) * K;
    unsigned long long acc[8][4] = {};

    {
        float4 aL = *(const float4*)(Ab + kb + lc);
        float4 aH = *(const float4*)(Ab + kb + lc + 4);
        As[0][lc + 0][lr] = aL.x; As[0][lc + 1][lr] = aL.y; As[0][lc + 2][lr] = aL.z; As[0][lc + 3][lr] = aL.w;
        As[0][lc + 4][lr] = aH.x; As[0][lc + 5][lr] = aH.y; As[0][lc + 6][lr] = aH.z; As[0][lc + 7][lr] = aH.w;
        float4 bL = (n0 + nb_ < N) ? *(const float4*)(B + (long)(kb + krow) * N + n0 + nb_)
                                   : make_float4(0.f, 0.f, 0.f, 0.f);
        float4 bH = (n0 + nb_ + 4 < N) ? *(const float4*)(B + (long)(kb + krow) * N + n0 + nb_ + 4)
                                       : make_float4(0.f, 0.f, 0.f, 0.f);
        *(float4*)&Bs[0][krow][nb_] = bL;
        *(float4*)&Bs[0][krow][nb_ + 4] = bH;
    }
    __syncthreads();

    int buf = 0;
    for (int k0 = kb; k0 < kend; k0 += 16) {
        bool nxt = (k0 + 16) < kend;
        float4 naL, naH, nbL, nbH;
        if (nxt) {
            naL = *(const float4*)(Ab + k0 + 16 + lc);
            naH = *(const float4*)(Ab + k0 + 16 + lc + 4);
            nbL = (n0 + nb_ < N) ? *(const float4*)(B + (long)(k0 + 16 + krow) * N + n0 + nb_)
                                 : make_float4(0.f, 0.f, 0.f, 0.f);
            nbH = (n0 + nb_ + 4 < N) ? *(const float4*)(B + (long)(k0 + 16 + krow) * N + n0 + nb_ + 4)
                                     : make_float4(0.f, 0.f, 0.f, 0.f);
        }
#pragma unroll
        for (int kk = 0; kk < 16; kk++) {
            float4 a0 = *(const float4*)&As[buf][kk][ty * 4];
            float4 a1 = *(const float4*)&As[buf][kk][64 + ty * 4];
            ulonglong2 b01 = *(const ulonglong2*)&Bs[buf][kk][tx * 4];
            ulonglong2 b23 = *(const ulonglong2*)&Bs[buf][kk][64 + tx * 4];
            float ar[8] = { a0.x, a0.y, a0.z, a0.w, a1.x, a1.y, a1.z, a1.w };
#pragma unroll
            for (int i = 0; i < 8; i++) {
                unsigned long long ap; DUP2(ap, ar[i]);
                FMA2(acc[i][0], ap, b01.x); FMA2(acc[i][1], ap, b01.y);
                FMA2(acc[i][2], ap, b23.x); FMA2(acc[i][3], ap, b23.y);
            }
        }
        if (nxt) {
            int bN = buf ^ 1;
            As[bN][lc + 0][lr] = naL.x; As[bN][lc + 1][lr] = naL.y; As[bN][lc + 2][lr] = naL.z; As[bN][lc + 3][lr] = naL.w;
            As[bN][lc + 4][lr] = naH.x; As[bN][lc + 5][lr] = naH.y; As[bN][lc + 6][lr] = naH.z; As[bN][lc + 7][lr] = naH.w;
            *(float4*)&Bs[bN][krow][nb_] = nbL;
            *(float4*)&Bs[bN][krow][nb_ + 4] = nbH;
            __syncthreads();
            buf = bN;
        }
    }

#pragma unroll
    for (int i = 0; i < 8; i++) {
        int m = m0 + (i < 4 ? ty * 4 + i : 64 + ty * 4 + i - 4);
        float* Cr = C + (long)m * N;
#pragma unroll
        for (int jp = 0; jp < 4; jp++) {
            int n = n0 + (jp < 2 ? tx * 4 + jp * 2 : 64 + tx * 4 + (jp - 2) * 2);
            if (n < N) *(unsigned long long*)(Cr + n) = acc[i][jp];
        }
    }
}

// ---------------- BN + lrelu reduce of 2 out partials (float4) ----------------
__global__ void bn_reduce(const float* __restrict__ P, float* __restrict__ out,
                          const float* __restrict__ gamma, const float* __restrict__ beta,
                          const float* __restrict__ rmean, const float* __restrict__ rvar) {
    int m = blockIdx.x;
    int g = m & 31;
    float sc = rsqrtf(rvar[g] + BN_EPS) * gamma[g];
    float mu = rmean[g], bt = beta[g];
    const float* p0 = P + (long)m * D2;
    float* o = out + (long)m * D2;
    for (int n4 = threadIdx.x; n4 < D2 / 4; n4 += 256) {
        float4 a = *(const float4*)(p0 + n4 * 4);
        float4 b = *(const float4*)(p0 + OSL + n4 * 4);
        float r[4] = { a.x + b.x, a.y + b.y, a.z + b.z, a.w + b.w };
#pragma unroll
        for (int j = 0; j < 4; j++) {
            float v = (r[j] - mu) * sc + bt;
            r[j] = (v >= 0.f) ? v : LEAK * v;
        }
        *(float4*)(o + n4 * 4) = make_float4(r[0], r[1], r[2], r[3]);
    }
}

// ============ fused argmin(VQ0, 4 partials) + conv1 + lrelu ============
__global__ void am0_conv1(const float* __restrict__ Sp, const float* __restrict__ cb_fdw) {
    int v = blockIdx.x;
    int i = v & 31;
    __shared__ float sd[256]; __shared__ int si[256];
    __shared__ float w[9];
    __shared__ int s_idx;
    if (threadIdx.x < 9) w[threadIdx.x] = g_qw1[i * 9 + threadIdx.x];
    float bd = 3.4e38f; int bk = 0;
    for (int k = threadIdx.x; k < NF; k += 256) {
        float s = 0.f;
#pragma unroll
        for (int sp = 0; sp < 4; sp++)
            s += Sp[((long)sp * NF + v) * NF + k];
        float d = g_nfdw[k] - 2.0f * s;
        if (d < bd) { bd = d; bk = k; }
    }
    sd[threadIdx.x] = bd; si[threadIdx.x] = bk; __syncthreads();
    for (int o = 128; o > 0; o >>= 1) {
        if (threadIdx.x < o) {
            float d2 = sd[threadIdx.x + o]; int k2 = si[threadIdx.x + o];
            if (d2 < sd[threadIdx.x] || (d2 == sd[threadIdx.x] && k2 < si[threadIdx.x])) {
                sd[threadIdx.x] = d2; si[threadIdx.x] = k2;
            }
        }
        __syncthreads();
    }
    if (threadIdx.x == 0) s_idx = si[0];
    __syncthreads();
    const float* src = cb_fdw + (long)s_idx * D0;
    for (int p = threadIdx.x; p < D1; p += 256) {
        int py = p / H2c, px = p - py * H2c;
        const float* s0 = src + py * H0c + px;
        float acc = s0[0] * w[0] + s0[1] * w[1] + s0[2] * w[2]
                  + s0[H0c] * w[3] + s0[H0c + 1] * w[4] + s0[H0c + 2] * w[5]
                  + s0[2 * H0c] * w[6] + s0[2 * H0c + 1] * w[7] + s0[2 * H0c + 2] * w[8];
        g_h1[(long)v * D1 + p] = (acc >= 0.f) ? acc : LEAK * acc;
    }
}

// ============ fused argmin(VQ1, 4 partials) + idx2 scan (DOT 4 partials) ============
__global__ void am1_idx2(const float* __restrict__ Vp, const float* __restrict__ DOT) {
    int vbi = blockIdx.x;
    int b = vbi >> 5, i = vbi & 31;
    __shared__ float sd[256]; __shared__ int si[256];
    __shared__ int s_j;
    float bd = 3.4e38f; int bk = 0;
    for (int k = threadIdx.x; k < NF; k += 256) {
        float s = 0.f;
#pragma unroll
        for (int sp = 0; sp < 4; sp++)
            s += Vp[((long)sp * NF + vbi) * NF + k];
        float d = g_nfpw[k] - 2.0f * s;
        if (d < bd) { bd = d; bk = k; }
    }
    sd[threadIdx.x] = bd; si[threadIdx.x] = bk; __syncthreads();
    for (int o = 128; o > 0; o >>= 1) {
        if (threadIdx.x < o) {
            float d2 = sd[threadIdx.x + o]; int k2 = si[threadIdx.x + o];
            if (d2 < sd[threadIdx.x] || (d2 == sd[threadIdx.x] && k2 < si[threadIdx.x])) {
                sd[threadIdx.x] = d2; si[threadIdx.x] = k2;
            }
        }
        __syncthreads();
    }
    if (threadIdx.x == 0) s_j = si[0];
    __syncthreads();
    int j = s_j;
    __shared__ float dr[NF]; __shared__ float nn[NF];
    for (int k = threadIdx.x; k < NF; k += 256) {
        float v = 0.f;
#pragma unroll
        for (int sp = 0; sp < 4; sp++)
            v += DOT[((long)sp * NF + j) * NF + k];
        dr[k] = v;
        nn[k] = g_nfdw2[k];
    }
    __syncthreads();
    int warp = threadIdx.x >> 5, lane = threadIdx.x & 31;
    for (int o = warp; o < CH; o += 8) {
        float s = g_qpw1[o * 32 + i];
        float bd2 = 3.4e38f; int bk2 = 0;
        for (int k = lane; k < NF; k += 32) {
            float d = nn[k] - 2.0f * s * dr[k];
            if (d < bd2) { bd2 = d; bk2 = k; }
        }
        for (int off = 16; off > 0; off >>= 1) {
            float d2 = __shfl_down_sync(0xffffffffu, bd2, off);
            int k2 = __shfl_down_sync(0xffffffffu, bk2, off);
            if (d2 < bd2 || (d2 == bd2 && k2 < bk2)) { bd2 = d2; bk2 = k2; }
        }
        if (lane == 0) g_idx2[b * OC + o * 32 + i] = bk2;
    }
}

// ---------------- pair argmin over m per (k,o), float4 G loads ----------------
__global__ void __launch_bounds__(256) pair_kernel() {
    int k = blockIdx.x;
    __shared__ float gs[9][NF];
    __shared__ float nn[NF];
    __shared__ float ws[CH * 9];
#pragma unroll
    for (int t = 0; t < 9; t++)
        for (int m4 = threadIdx.x; m4 < NF / 4; m4 += 256)
            *(float4*)&gs[t][m4 * 4] = *(const float4*)&g_G[((long)t * NF + k) * NF + m4 * 4];
    for (int m4 = threadIdx.x; m4 < NF / 4; m4 += 256)
        *(float4*)&nn[m4 * 4] = *(const float4*)&g_nfpw2[m4 * 4];
    for (int i = threadIdx.x; i < CH * 9; i += 256) ws[i] = g_qw2[i];
    __syncthreads();
    int warp = threadIdx.x >> 5, lane = threadIdx.x & 31;
    for (int o = warp; o < CH; o += 8) {
        float wv[9];
#pragma unroll
        for (int t = 0; t < 9; t++) wv[t] = ws[o * 9 + t];
        float bd = 3.4e38f; int bk = 0;
        for (int m = lane; m < NF; m += 32) {
            float T = 0.f;
#pragma unroll
            for (int t = 0; t < 9; t++) T += wv[t] * gs[t][m];
            float d = nn[m] - 2.0f * T;
            if (d < bd) { bd = d; bk = m; }
        }
        for (int off = 16; off > 0; off >>= 1) {
            float d2 = __shfl_down_sync(0xffffffffu, bd, off);
            int k2 = __shfl_down_sync(0xffffffffu, bk, off);
            if (d2 < bd || (d2 == bd && k2 < bk)) { bd = d2; bk = k2; }
        }
        if (lane == 0) g_pair[k * CH + o] = bk;
    }
}

// ---------------- histogram ----------------
__global__ void cnt_kernel() {
    int bo = blockIdx.x;
    __shared__ int c[NF];
    for (int m = threadIdx.x; m < NF; m += 256) c[m] = 0;
    __syncthreads();
    if (threadIdx.x == 0) {
        int b = bo >> 5, o = bo & 31;
        for (int i = 0; i < 32; i++) {
            int k2 = g_idx2[b * OC + o * 32 + i];
            c[g_pair[k2 * CH + o]]++;
        }
    }
    __syncthreads();
    for (int m = threadIdx.x; m < NF; m += 256) g_cnt[(long)bo * NF + m] = c[m];
}

// ---------------- A[bg][m] = sum_o qpw2[g*32+o] * cnt[b][o][m] ----------------
__global__ void A_kernel() {
    int bg = blockIdx.x;
    int b = bg >> 5, g = bg & 31;
    __shared__ float w[32];
    if (threadIdx.x < 32) w[threadIdx.x] = g_qpw2[g * 32 + threadIdx.x];
    __syncthreads();
    for (int m = threadIdx.x; m < NF; m += 256) {
        float acc = 0.f;
#pragma unroll
        for (int o = 0; o < 32; o++)
            acc += w[o] * (float)g_cnt[((long)(b * 32 + o)) * NF + m];
        g_A[(long)bg * NF + m] = acc;
    }
}

extern "C" void kernel_launch(void* const* d_in, const int* in_sizes, int n_in,
                              void* d_out, int out_size) {
    const float* x       = (const float*)d_in[0];
    const float* dw_w1   = (const float*)d_in[1];
    const float* pw_w1   = (const float*)d_in[2];
    const float* dw_w2   = (const float*)d_in[3];
    const float* pw_w2   = (const float*)d_in[4];
    const float* cb_dw   = (const float*)d_in[5];
    const float* cb_pw   = (const float*)d_in[6];
    const float* cb_dw2  = (const float*)d_in[7];
    const float* cb_pw2  = (const float*)d_in[8];
    const float* cb_fdw  = (const float*)d_in[9];
    const float* cb_fpw  = (const float*)d_in[10];
    const float* cb_fdw2 = (const float*)d_in[11];
    const float* cb_fpw2 = (const float*)d_in[12];
    const float* gamma   = (const float*)d_in[13];
    const float* beta    = (const float*)d_in[14];
    const float* rmean   = (const float*)d_in[15];
    const float* rvar    = (const float*)d_in[16];
    float* out = (float*)d_out;

    float *pSp, *pCs, *pA;
    cudaGetSymbolAddress((void**)&pSp, g_Sp);
    cudaGetSymbolAddress((void**)&pCs, g_Cs);
    cudaGetSymbolAddress((void**)&pA, g_A);

    static cudaStream_t s1 = [] { cudaStream_t s; cudaStreamCreateWithFlags(&s, cudaStreamNonBlocking); return s; }();
    static cudaEvent_t eFork  = [] { cudaEvent_t e; cudaEventCreateWithFlags(&e, cudaEventDisableTiming); return e; }();
    static cudaEvent_t ePrepA = [] { cudaEvent_t e; cudaEventCreateWithFlags(&e, cudaEventDisableTiming); return e; }();
    static cudaEvent_t ePair  = [] { cudaEvent_t e; cudaEventCreateWithFlags(&e, cudaEventDisableTiming); return e; }();

    cudaEventRecord(eFork, 0);
    cudaStreamWaitEvent(s1, eFork, 0);

    // aux chain: prepB (Cs shift) -> G  [starts immediately]
    prepB_kernel<<<9 * NF, 256, 0, s1>>>(cb_fdw2);
    gemm_g<<<dim3(4, 4, 9), 256, 0, s1>>>(cb_fpw2);

    // main: prepA first (tiny), then VQ0 + DOT1 co-run with aux's prepB/G
    prepA_kernel<<<4 * NF + 1, 256>>>(cb_fdw, cb_fpw, cb_fdw2, cb_fpw2,
                                      dw_w1, pw_w1, dw_w2, pw_w2,
                                      cb_dw, cb_pw, cb_dw2, cb_pw2);
    cudaEventRecord(ePrepA, 0);

    // aux: pair needs qw2/nfpw2 from prepA
    cudaStreamWaitEvent(s1, ePrepA, 0);
    pair_kernel<<<NF, 256, 0, s1>>>();
    cudaEventRecord(ePair, s1);

    // main chain continues
    gemm_vq0<<<dim3(4, 4, 4), 256>>>(x, cb_fdw);
    gemm_dot1<<<dim3(4, 4, 4), 256>>>(cb_fpw, cb_fdw2);
    am0_conv1<<<BI, 256>>>(pSp, cb_fdw);
    gemm_vq1<<<dim3(4, 4, 4), 256>>>(cb_fpw);
    am1_idx2<<<BI, 256>>>(pSp, pSp + 8L * NN2);
    cudaStreamWaitEvent(0, ePair, 0);
    cnt_kernel<<<B_ * CH, 256>>>();
    A_kernel<<<BI, 256>>>();
    sgemm_nn_split<<<dim3(16, 4, 2), 256>>>(pA, cb_fpw2, pCs);
    bn_reduce<<<BI, 256>>>(pCs, out, gamma, beta, rmean, rvar);
}